// round 6
// baseline (speedup 1.0000x reference)
#include <cuda_runtime.h>
#include <cstdint>
#include <math.h>

#define D_MODEL 1024
#define NHEADS  16
#define DEPTH   64
#define BATCH   2
#define SEQ     2048
#define MTOT    (BATCH*SEQ)   // 4096

// ---------------- scratch (device globals; no allocations allowed) ----------
__device__ float g_q[BATCH*NHEADS*SEQ*DEPTH];   // 16 MB, [B,H,S,64]
__device__ float g_k[BATCH*NHEADS*SEQ*DEPTH];
__device__ float g_v[BATCH*NHEADS*SEQ*DEPTH];
__device__ float g_ctx[BATCH*SEQ*D_MODEL];      // 16 MB, [B,S,1024]

// ---------------- helpers ----------------------------------------------------
__device__ __forceinline__ uint32_t f2tf32(float x) {
    uint32_t r;
    asm("cvt.rna.tf32.f32 %0, %1;" : "=r"(r) : "f"(x));
    return r;
}
__device__ __forceinline__ void mma_tf32_16x8x8(float* d, const uint32_t* a,
                                                const uint32_t* b) {
    asm volatile(
        "mma.sync.aligned.m16n8k8.row.col.f32.tf32.tf32.f32 "
        "{%0,%1,%2,%3}, {%4,%5,%6,%7}, {%8,%9}, {%0,%1,%2,%3};"
        : "+f"(d[0]), "+f"(d[1]), "+f"(d[2]), "+f"(d[3])
        : "r"(a[0]), "r"(a[1]), "r"(a[2]), "r"(a[3]), "r"(b[0]), "r"(b[1]));
}
__device__ __forceinline__ uint32_t smem_u32(const void* p) {
    uint32_t a;
    asm("{ .reg .u64 t; cvta.to.shared.u64 t, %1; cvt.u32.u64 %0, t; }"
        : "=r"(a) : "l"(p));
    return a;
}
#define CP_ASYNC16(sa, ga) \
    asm volatile("cp.async.ca.shared.global [%0], [%1], 16;" :: "r"(sa), "l"(ga))
#define CP_COMMIT() asm volatile("cp.async.commit_group;" ::: "memory")
#define CP_WAIT(n)  asm volatile("cp.async.wait_group %0;" :: "n"(n) : "memory")

// ============ tf32 tensor-core projection (cp.async pipelined) ==============
// out = A[M,K] @ W[N,K]^T + bias. CTA 128x128, 8 warps (2x4), warp 64x32.
// 2-stage cp.async double buffer of raw fp32; cvt at fragment load.
constexpr int PBM = 128, PBN = 128, PBK = 32, PLD = PBK + 4;   // PLD=36
constexpr int PROJ_STAGE = PBM * PLD;                           // floats
constexpr int PROJ_SMEM  = 4 * PROJ_STAGE * 4;                  // 73728 bytes

template<int SPLIT>
__device__ __forceinline__
void proj_body(float* smf, const float* __restrict__ A, const float* __restrict__ W,
               const float* __restrict__ bias, float* __restrict__ out) {
    const int tid  = threadIdx.x;
    const int wid  = tid >> 5;
    const int lane = tid & 31;
    const int g    = lane >> 2;
    const int tg   = lane & 3;
    const int wm   = wid >> 2;
    const int wn   = wid & 3;
    const int bm   = blockIdx.y * PBM;
    const int bn   = blockIdx.x * PBN;

    float* As0 = smf;
    float* Bs0 = smf + 2 * PROJ_STAGE;

    float acc[4][4][4] = {};

    // issue stage s into buffer s&1
    auto issue = [&](int s) {
        const int buf = s & 1;
        const int k0  = s * PBK;
        float* As = As0 + buf * PROJ_STAGE;
        float* Bs = Bs0 + buf * PROJ_STAGE;
        #pragma unroll
        for (int i = 0; i < 4; i++) {
            const int idx = tid + i * 256;
            const int r = idx >> 3;
            const int c = (idx & 7) * 4;
            CP_ASYNC16(smem_u32(&As[r * PLD + c]), A + (size_t)(bm + r) * D_MODEL + k0 + c);
            CP_ASYNC16(smem_u32(&Bs[r * PLD + c]), W + (size_t)(bn + r) * D_MODEL + k0 + c);
        }
        CP_COMMIT();
    };

    issue(0);
    for (int s = 0; s < D_MODEL / PBK; s++) {
        const int buf = s & 1;
        if (s + 1 < D_MODEL / PBK) { issue(s + 1); CP_WAIT(1); }
        else                       { CP_WAIT(0); }
        __syncthreads();

        const float* As = As0 + buf * PROJ_STAGE;
        const float* Bs = Bs0 + buf * PROJ_STAGE;
        #pragma unroll
        for (int ks = 0; ks < PBK; ks += 8) {
            uint32_t afr[4][4], bfr[4][2];
            #pragma unroll
            for (int mi = 0; mi < 4; mi++) {
                const float* pa = &As[(wm * 64 + mi * 16 + g) * PLD + ks + tg];
                afr[mi][0] = f2tf32(pa[0]);
                afr[mi][1] = f2tf32(pa[8 * PLD]);
                afr[mi][2] = f2tf32(pa[4]);
                afr[mi][3] = f2tf32(pa[8 * PLD + 4]);
            }
            #pragma unroll
            for (int ni = 0; ni < 4; ni++) {
                const float* pb = &Bs[(wn * 32 + ni * 8 + g) * PLD + ks + tg];
                bfr[ni][0] = f2tf32(pb[0]);
                bfr[ni][1] = f2tf32(pb[4]);
            }
            #pragma unroll
            for (int mi = 0; mi < 4; mi++)
                #pragma unroll
                for (int ni = 0; ni < 4; ni++)
                    mma_tf32_16x8x8(acc[mi][ni], afr[mi], bfr[ni]);
        }
        __syncthreads();
    }

    #pragma unroll
    for (int mi = 0; mi < 4; mi++) {
        #pragma unroll
        for (int ni = 0; ni < 4; ni++) {
            const int col = bn + wn * 32 + ni * 8 + tg * 2;
            const float2 bv = *(const float2*)(bias + col);
            #pragma unroll
            for (int half = 0; half < 2; half++) {
                const int m = bm + wm * 64 + mi * 16 + g + half * 8;
                float2 o;
                o.x = acc[mi][ni][half * 2 + 0] + bv.x;
                o.y = acc[mi][ni][half * 2 + 1] + bv.y;
                if (SPLIT) {
                    const int b = m >> 11, sq = m & 2047;
                    const int h = col >> 6, d = col & 63;
                    *(float2*)(out + (((size_t)(b * NHEADS + h) * SEQ) + sq) * DEPTH + d) = o;
                } else {
                    *(float2*)(out + (size_t)m * D_MODEL + col) = o;
                }
            }
        }
    }
}

__global__ __launch_bounds__(256)
void proj_qkv(const float* __restrict__ q, const float* __restrict__ k,
              const float* __restrict__ v,
              const float* __restrict__ Wq, const float* __restrict__ bq,
              const float* __restrict__ Wk, const float* __restrict__ bk,
              const float* __restrict__ Wv, const float* __restrict__ bv) {
    extern __shared__ float smf[];
    const float *A, *W, *bias;
    float* out;
    if (blockIdx.z == 0)      { A = q; W = Wq; bias = bq; out = g_q; }
    else if (blockIdx.z == 1) { A = k; W = Wk; bias = bk; out = g_k; }
    else                      { A = v; W = Wv; bias = bv; out = g_v; }
    proj_body<1>(smf, A, W, bias, out);
}

__global__ __launch_bounds__(256)
void proj_o(const float* __restrict__ W, const float* __restrict__ bias,
            float* __restrict__ out) {
    extern __shared__ float smf[];
    proj_body<0>(smf, g_ctx, W, bias, out);
}

// ================= tensor-core flash attention v4 ============================
// CTA: 256 threads (8 warps). Q tile 128 rows (16/warp), K tile 64 per iter.
// Q/K stored k-interleaved (pos p -> slot p<4 ? 2p : 2(p-4)+1) so fragment
// pairs (tg, tg+4) are adjacent -> uint2 loads halve QK fragment LDS count.
// K/V prefetched into registers one iteration ahead. QK^T split-precision.
constexpr int FQ  = 128;
constexpr int FK  = 64;
constexpr int FLD = 68;

constexpr int W_QHI = 0;
constexpr int W_QLO = W_QHI + FQ * FLD;   // 8704
constexpr int W_K   = W_QLO + FQ * FLD;   // 17408
constexpr int W_V   = W_K   + FK * FLD;   // 21760
constexpr int W_P   = W_V   + FK * FLD;   // 26112
constexpr int W_PEN = W_P   + FQ * FLD;   // 34816
constexpr int FLASH_SMEM = (W_PEN + FK) * 4;   // 139520 bytes

__global__ __launch_bounds__(256)
void flash_mma(const int* __restrict__ mask) {
    extern __shared__ uint32_t sw[];
    float* pen = (float*)(sw + W_PEN);

    const int qt = blockIdx.x, h = blockIdx.y, b = blockIdx.z;
    const int tid  = threadIdx.x;
    const int w    = tid >> 5;
    const int lane = tid & 31;
    const int g    = lane >> 2;
    const int tg   = lane & 3;

    const float* qbase = g_q + ((size_t)(b*NHEADS + h) * SEQ + qt*FQ) * DEPTH;
    const float* kbase = g_k + (size_t)(b*NHEADS + h) * SEQ * DEPTH;
    const float* vbase = g_v + (size_t)(b*NHEADS + h) * SEQ * DEPTH;

    // stage Q (scaled by 1/8), split into tf32 hi+lo, k-interleaved columns
    #pragma unroll
    for (int i = 0; i < 8; i++) {
        const int idx = tid + i * 256;
        const int r = idx >> 4, c4 = (idx & 15) << 2;
        float4 v = *(const float4*)(qbase + r * DEPTH + c4);
        float xs[4] = {v.x * 0.125f, v.y * 0.125f, v.z * 0.125f, v.w * 0.125f};
        uint32_t hi[4], lo[4];
        #pragma unroll
        for (int e = 0; e < 4; e++) {
            hi[e] = f2tf32(xs[e]);
            lo[e] = f2tf32(xs[e] - __uint_as_float(hi[e]));
        }
        const int base = (c4 & ~7) + ((c4 & 4) ? 1 : 0);   // interleave slot base
        uint32_t* dh = sw + W_QHI + r * FLD + base;
        uint32_t* dl = sw + W_QLO + r * FLD + base;
        dh[0] = hi[0]; dh[2] = hi[1]; dh[4] = hi[2]; dh[6] = hi[3];
        dl[0] = lo[0]; dl[2] = lo[1]; dl[4] = lo[2]; dl[6] = lo[3];
    }

    // prefetch K/V tile 0 into registers + mask word
    float4 kreg[4], vreg[4];
    #pragma unroll
    for (int j = 0; j < 4; j++) {
        const int slot = tid + j * 256;
        const int r = slot >> 4, c4 = (slot & 15) << 2;
        kreg[j] = *(const float4*)(kbase + (size_t)r * DEPTH + c4);
        vreg[j] = *(const float4*)(vbase + (size_t)r * DEPTH + c4);
    }
    int pmask = (tid < FK) ? mask[b*SEQ + tid] : 0;

    float m0 = -1e30f, m1 = -1e30f, l0 = 0.f, l1 = 0.f;
    float oac[8][4] = {};

    for (int kt = 0; kt < SEQ / FK; kt++) {
        __syncthreads();   // prev iter's MMAs done with K/V/P smem; Q stores done
        #pragma unroll
        for (int j = 0; j < 4; j++) {
            const int slot = tid + j * 256;
            const int r = slot >> 4, c4 = (slot & 15) << 2;
            // K: k-interleaved scalar stores
            const int base = (c4 & ~7) + ((c4 & 4) ? 1 : 0);
            uint32_t* dk = sw + W_K + r * FLD + base;
            dk[0] = f2tf32(kreg[j].x); dk[2] = f2tf32(kreg[j].y);
            dk[4] = f2tf32(kreg[j].z); dk[6] = f2tf32(kreg[j].w);
            // V: natural layout (float4)
            uint4 vt = make_uint4(f2tf32(vreg[j].x), f2tf32(vreg[j].y),
                                  f2tf32(vreg[j].z), f2tf32(vreg[j].w));
            *(uint4*)(sw + W_V + r * FLD + c4) = vt;
        }
        if (tid < FK)
            pen[tid] = -1e9f * (float)pmask;
        __syncthreads();

        // prefetch next tile (consumed next iteration; overlaps with MMAs)
        if (kt + 1 < SEQ / FK) {
            const float* kb2 = kbase + (size_t)(kt + 1) * FK * DEPTH;
            const float* vb2 = vbase + (size_t)(kt + 1) * FK * DEPTH;
            #pragma unroll
            for (int j = 0; j < 4; j++) {
                const int slot = tid + j * 256;
                const int r = slot >> 4, c4 = (slot & 15) << 2;
                kreg[j] = *(const float4*)(kb2 + (size_t)r * DEPTH + c4);
                vreg[j] = *(const float4*)(vb2 + (size_t)r * DEPTH + c4);
            }
            if (tid < FK) pmask = mask[b*SEQ + (kt + 1)*FK + tid];
        }

        // ---- S = Q @ K^T (split-precision, paired uint2 fragment loads) ----
        float sac[8][4] = {};
        #pragma unroll
        for (int ks = 0; ks < 8; ks++) {
            uint32_t ahi[4], alo[4];
            const uint32_t* qh = sw + W_QHI + (w*16 + g) * FLD + ks*8 + 2*tg;
            const uint32_t* ql = sw + W_QLO + (w*16 + g) * FLD + ks*8 + 2*tg;
            const uint2 h0 = *(const uint2*)qh;
            const uint2 h1 = *(const uint2*)(qh + 8*FLD);
            const uint2 l0v = *(const uint2*)ql;
            const uint2 l1v = *(const uint2*)(ql + 8*FLD);
            ahi[0] = h0.x; ahi[1] = h1.x; ahi[2] = h0.y; ahi[3] = h1.y;
            alo[0] = l0v.x; alo[1] = l1v.x; alo[2] = l0v.y; alo[3] = l1v.y;
            #pragma unroll
            for (int nf = 0; nf < 8; nf++) {
                const uint2 bb = *(const uint2*)(sw + W_K + (nf*8 + g) * FLD + ks*8 + 2*tg);
                uint32_t bf[2] = {bb.x, bb.y};
                mma_tf32_16x8x8(sac[nf], ahi, bf);
                mma_tf32_16x8x8(sac[nf], alo, bf);
            }
        }

        // ---- mask + online softmax ----
        #pragma unroll
        for (int nf = 0; nf < 8; nf++) {
            const float2 pe = *(const float2*)&pen[nf*8 + 2*tg];
            sac[nf][0] += pe.x; sac[nf][1] += pe.y;
            sac[nf][2] += pe.x; sac[nf][3] += pe.y;
        }
        float mx0 = -1e30f, mx1 = -1e30f;
        #pragma unroll
        for (int nf = 0; nf < 8; nf++) {
            mx0 = fmaxf(mx0, fmaxf(sac[nf][0], sac[nf][1]));
            mx1 = fmaxf(mx1, fmaxf(sac[nf][2], sac[nf][3]));
        }
        mx0 = fmaxf(mx0, __shfl_xor_sync(0xffffffffu, mx0, 1));
        mx0 = fmaxf(mx0, __shfl_xor_sync(0xffffffffu, mx0, 2));
        mx1 = fmaxf(mx1, __shfl_xor_sync(0xffffffffu, mx1, 1));
        mx1 = fmaxf(mx1, __shfl_xor_sync(0xffffffffu, mx1, 2));
        const float mn0 = fmaxf(m0, mx0), mn1 = fmaxf(m1, mx1);
        const float c0 = __expf(m0 - mn0), c1 = __expf(m1 - mn1);
        float s0 = 0.f, s1 = 0.f;
        #pragma unroll
        for (int nf = 0; nf < 8; nf++) {
            const float e0 = __expf(sac[nf][0] - mn0);
            const float e1 = __expf(sac[nf][1] - mn0);
            const float e2 = __expf(sac[nf][2] - mn1);
            const float e3 = __expf(sac[nf][3] - mn1);
            s0 += e0 + e1; s1 += e2 + e3;
            uint2 r0; r0.x = f2tf32(e0); r0.y = f2tf32(e1);
            uint2 r1; r1.x = f2tf32(e2); r1.y = f2tf32(e3);
            *(uint2*)(sw + W_P + (w*16 + g    ) * FLD + nf*8 + 2*tg) = r0;
            *(uint2*)(sw + W_P + (w*16 + g + 8) * FLD + nf*8 + 2*tg) = r1;
        }
        s0 += __shfl_xor_sync(0xffffffffu, s0, 1);
        s0 += __shfl_xor_sync(0xffffffffu, s0, 2);
        s1 += __shfl_xor_sync(0xffffffffu, s1, 1);
        s1 += __shfl_xor_sync(0xffffffffu, s1, 2);
        l0 = l0 * c0 + s0; l1 = l1 * c1 + s1;
        m0 = mn0; m1 = mn1;
        #pragma unroll
        for (int nf = 0; nf < 8; nf++) {
            oac[nf][0] *= c0; oac[nf][1] *= c0;
            oac[nf][2] *= c1; oac[nf][3] *= c1;
        }
        __syncwarp();   // P stores (cross-lane within warp) visible

        // ---- O += P @ V (P/V natural layouts) ----
        #pragma unroll
        for (int ks = 0; ks < 8; ks++) {
            uint32_t a[4];
            const uint32_t* pp = sw + W_P + (w*16 + g) * FLD + ks*8 + tg;
            a[0] = pp[0]; a[1] = pp[8*FLD]; a[2] = pp[4]; a[3] = pp[8*FLD + 4];
            #pragma unroll
            for (int nf = 0; nf < 8; nf++) {
                uint32_t bf[2];
                const uint32_t* vp = sw + W_V + (ks*8 + tg) * FLD + nf*8 + g;
                bf[0] = vp[0]; bf[1] = vp[4*FLD];
                mma_tf32_16x8x8(oac[nf], a, bf);
            }
        }
    }

    // epilogue: merged-head context [B,S,1024]
    const float il0 = 1.0f / l0, il1 = 1.0f / l1;
    const int row0 = qt*FQ + w*16 + g;
    float* ob = g_ctx + ((size_t)b*SEQ + row0) * D_MODEL + h*DEPTH;
    #pragma unroll
    for (int nf = 0; nf < 8; nf++) {
        const int c = nf*8 + 2*tg;
        float2 o0; o0.x = oac[nf][0] * il0; o0.y = oac[nf][1] * il0;
        float2 o1; o1.x = oac[nf][2] * il1; o1.y = oac[nf][3] * il1;
        *(float2*)(ob + c) = o0;
        *(float2*)(ob + (size_t)8 * D_MODEL + c) = o1;
    }
}

// ---------------------------------------------------------------------------
extern "C" void kernel_launch(void* const* d_in, const int* in_sizes, int n_in,
                              void* d_out, int out_size) {
    const float* query = (const float*)d_in[0];
    const float* key   = (const float*)d_in[1];
    const float* value = (const float*)d_in[2];
    const int*   mask  = (const int*)  d_in[3];
    const float* Wq = (const float*)d_in[4];
    const float* bq = (const float*)d_in[5];
    const float* Wk = (const float*)d_in[6];
    const float* bk = (const float*)d_in[7];
    const float* Wv = (const float*)d_in[8];
    const float* bv = (const float*)d_in[9];
    const float* Wo = (const float*)d_in[10];
    const float* bo = (const float*)d_in[11];
    float* out = (float*)d_out;

    cudaFuncSetAttribute(proj_qkv, cudaFuncAttributeMaxDynamicSharedMemorySize, PROJ_SMEM);
    cudaFuncSetAttribute(proj_o,   cudaFuncAttributeMaxDynamicSharedMemorySize, PROJ_SMEM);
    cudaFuncSetAttribute(flash_mma, cudaFuncAttributeMaxDynamicSharedMemorySize, FLASH_SMEM);

    const dim3 gq(D_MODEL / PBN, MTOT / PBM, 3);   // (8, 32, 3)
    proj_qkv<<<gq, 256, PROJ_SMEM>>>(query, key, value, Wq, bq, Wk, bk, Wv, bv);

    flash_mma<<<dim3(SEQ/FQ, NHEADS, BATCH), 256, FLASH_SMEM>>>(mask);

    proj_o<<<dim3(D_MODEL / PBN, MTOT / PBM), 256, PROJ_SMEM>>>(Wo, bo, out);
}

// round 7
// speedup vs baseline: 1.1142x; 1.1142x over previous
#include <cuda_runtime.h>
#include <cstdint>
#include <math.h>

#define D_MODEL 1024
#define NHEADS  16
#define DEPTH   64
#define BATCH   2
#define SEQ     2048
#define MTOT    (BATCH*SEQ)   // 4096

// ---------------- scratch (device globals; no allocations allowed) ----------
__device__ float g_q[BATCH*NHEADS*SEQ*DEPTH];   // 16 MB, [B,H,S,64]
__device__ float g_k[BATCH*NHEADS*SEQ*DEPTH];
__device__ float g_v[BATCH*NHEADS*SEQ*DEPTH];
__device__ float g_ctx[BATCH*SEQ*D_MODEL];      // 16 MB, [B,S,1024]

// ---------------- helpers ----------------------------------------------------
__device__ __forceinline__ uint32_t f2tf32(float x) {
    uint32_t r;
    asm("cvt.rna.tf32.f32 %0, %1;" : "=r"(r) : "f"(x));
    return r;
}
__device__ __forceinline__ void mma_tf32_16x8x8(float* d, const uint32_t* a,
                                                const uint32_t* b) {
    asm volatile(
        "mma.sync.aligned.m16n8k8.row.col.f32.tf32.tf32.f32 "
        "{%0,%1,%2,%3}, {%4,%5,%6,%7}, {%8,%9}, {%0,%1,%2,%3};"
        : "+f"(d[0]), "+f"(d[1]), "+f"(d[2]), "+f"(d[3])
        : "r"(a[0]), "r"(a[1]), "r"(a[2]), "r"(a[3]), "r"(b[0]), "r"(b[1]));
}
__device__ __forceinline__ void ldm_x4(uint32_t* r, uint32_t saddr) {
    asm volatile("ldmatrix.sync.aligned.m8n8.x4.shared.b16 {%0,%1,%2,%3}, [%4];"
        : "=r"(r[0]), "=r"(r[1]), "=r"(r[2]), "=r"(r[3]) : "r"(saddr));
}
__device__ __forceinline__ uint32_t smem_u32(const void* p) {
    uint32_t a;
    asm("{ .reg .u64 t; cvta.to.shared.u64 t, %1; cvt.u32.u64 %0, t; }"
        : "=r"(a) : "l"(p));
    return a;
}
#define CP_ASYNC16(sa, ga) \
    asm volatile("cp.async.ca.shared.global [%0], [%1], 16;" :: "r"(sa), "l"(ga))
#define CP_COMMIT() asm volatile("cp.async.commit_group;" ::: "memory")
#define CP_WAIT(n)  asm volatile("cp.async.wait_group %0;" :: "n"(n) : "memory")

// ============ tf32 tensor-core projection (cp.async pipelined) ==============
constexpr int PBM = 128, PBN = 128, PBK = 32, PLD = PBK + 4;   // PLD=36
constexpr int PROJ_STAGE = PBM * PLD;                           // floats
constexpr int PROJ_SMEM  = 4 * PROJ_STAGE * 4;                  // 73728 bytes

template<int SPLIT>
__device__ __forceinline__
void proj_body(float* smf, const float* __restrict__ A, const float* __restrict__ W,
               const float* __restrict__ bias, float* __restrict__ out) {
    const int tid  = threadIdx.x;
    const int wid  = tid >> 5;
    const int lane = tid & 31;
    const int g    = lane >> 2;
    const int tg   = lane & 3;
    const int wm   = wid >> 2;
    const int wn   = wid & 3;
    const int bm   = blockIdx.y * PBM;
    const int bn   = blockIdx.x * PBN;

    // ldmatrix per-lane address components
    const int lrow8 = lane & 7;
    const int lhalf = (lane >> 3) & 1;   // 0/1 -> row+8 (A) / col+4 (B)
    const int lquad = lane >> 4;         // 0/1 -> col+4 (A) / ni pair (B)

    float* As0 = smf;
    float* Bs0 = smf + 2 * PROJ_STAGE;
    const uint32_t smb = smem_u32(smf);

    // base byte addrs (buffer 0)
    uint32_t aAddr[4], bAddr[2];
    #pragma unroll
    for (int mi = 0; mi < 4; mi++)
        aAddr[mi] = smb + ((wm*64 + mi*16 + lhalf*8 + lrow8) * PLD + lquad*4) * 4;
    #pragma unroll
    for (int u = 0; u < 2; u++)
        bAddr[u] = smb + (2*PROJ_STAGE + (wn*32 + (2*u + lquad)*8 + lrow8) * PLD + lhalf*4) * 4;

    float acc[4][4][4] = {};

    auto issue = [&](int s) {
        const int buf = s & 1;
        const int k0  = s * PBK;
        float* As = As0 + buf * PROJ_STAGE;
        float* Bs = Bs0 + buf * PROJ_STAGE;
        #pragma unroll
        for (int i = 0; i < 4; i++) {
            const int idx = tid + i * 256;
            const int r = idx >> 3;
            const int c = (idx & 7) * 4;
            CP_ASYNC16(smem_u32(&As[r * PLD + c]), A + (size_t)(bm + r) * D_MODEL + k0 + c);
            CP_ASYNC16(smem_u32(&Bs[r * PLD + c]), W + (size_t)(bn + r) * D_MODEL + k0 + c);
        }
        CP_COMMIT();
    };

    issue(0);
    for (int s = 0; s < D_MODEL / PBK; s++) {
        const uint32_t bufo = (uint32_t)(s & 1) * PROJ_STAGE * 4;
        if (s + 1 < D_MODEL / PBK) { issue(s + 1); CP_WAIT(1); }
        else                       { CP_WAIT(0); }
        __syncthreads();

        #pragma unroll
        for (int ks = 0; ks < PBK; ks += 8) {
            uint32_t araw[4][4], braw[2][4];
            #pragma unroll
            for (int mi = 0; mi < 4; mi++) ldm_x4(araw[mi], aAddr[mi] + bufo + ks*4);
            #pragma unroll
            for (int u = 0; u < 2; u++)    ldm_x4(braw[u],  bAddr[u]  + bufo + ks*4);

            uint32_t afr[4][4], bfr[4][2];
            #pragma unroll
            for (int mi = 0; mi < 4; mi++)
                #pragma unroll
                for (int e = 0; e < 4; e++)
                    afr[mi][e] = f2tf32(__uint_as_float(araw[mi][e]));
            #pragma unroll
            for (int u = 0; u < 2; u++) {
                bfr[2*u  ][0] = f2tf32(__uint_as_float(braw[u][0]));
                bfr[2*u  ][1] = f2tf32(__uint_as_float(braw[u][1]));
                bfr[2*u+1][0] = f2tf32(__uint_as_float(braw[u][2]));
                bfr[2*u+1][1] = f2tf32(__uint_as_float(braw[u][3]));
            }
            #pragma unroll
            for (int mi = 0; mi < 4; mi++)
                #pragma unroll
                for (int ni = 0; ni < 4; ni++)
                    mma_tf32_16x8x8(acc[mi][ni], afr[mi], bfr[ni]);
        }
        __syncthreads();
    }

    #pragma unroll
    for (int mi = 0; mi < 4; mi++) {
        #pragma unroll
        for (int ni = 0; ni < 4; ni++) {
            const int col = bn + wn * 32 + ni * 8 + tg * 2;
            const float2 bv = *(const float2*)(bias + col);
            #pragma unroll
            for (int half = 0; half < 2; half++) {
                const int m = bm + wm * 64 + mi * 16 + g + half * 8;
                float2 o;
                o.x = acc[mi][ni][half * 2 + 0] + bv.x;
                o.y = acc[mi][ni][half * 2 + 1] + bv.y;
                if (SPLIT) {
                    const int b = m >> 11, sq = m & 2047;
                    const int h = col >> 6, d = col & 63;
                    *(float2*)(out + (((size_t)(b * NHEADS + h) * SEQ) + sq) * DEPTH + d) = o;
                } else {
                    *(float2*)(out + (size_t)m * D_MODEL + col) = o;
                }
            }
        }
    }
}

__global__ __launch_bounds__(256)
void proj_qkv(const float* __restrict__ q, const float* __restrict__ k,
              const float* __restrict__ v,
              const float* __restrict__ Wq, const float* __restrict__ bq,
              const float* __restrict__ Wk, const float* __restrict__ bk,
              const float* __restrict__ Wv, const float* __restrict__ bv) {
    extern __shared__ float smf[];
    const float *A, *W, *bias;
    float* out;
    if (blockIdx.z == 0)      { A = q; W = Wq; bias = bq; out = g_q; }
    else if (blockIdx.z == 1) { A = k; W = Wk; bias = bk; out = g_k; }
    else                      { A = v; W = Wv; bias = bv; out = g_v; }
    proj_body<1>(smf, A, W, bias, out);
}

__global__ __launch_bounds__(256)
void proj_o(const float* __restrict__ W, const float* __restrict__ bias,
            float* __restrict__ out) {
    extern __shared__ float smf[];
    proj_body<0>(smf, g_ctx, W, bias, out);
}

// ================= tensor-core flash attention v5 ============================
// R5 layouts/staging (natural, uint4 stores) + ldmatrix fragment loads.
constexpr int FQ  = 128;
constexpr int FK  = 64;
constexpr int FLD = 68;

constexpr int W_QHI = 0;
constexpr int W_QLO = W_QHI + FQ * FLD;   // 8704
constexpr int W_K   = W_QLO + FQ * FLD;   // 17408
constexpr int W_V   = W_K   + FK * FLD;   // 21760
constexpr int W_P   = W_V   + FK * FLD;   // 26112
constexpr int W_PEN = W_P   + FQ * FLD;   // 34816
constexpr int FLASH_SMEM = (W_PEN + FK) * 4;   // 139520 bytes

__global__ __launch_bounds__(256)
void flash_mma(const int* __restrict__ mask) {
    extern __shared__ uint32_t sw[];
    float* pen = (float*)(sw + W_PEN);

    const int qt = blockIdx.x, h = blockIdx.y, b = blockIdx.z;
    const int tid  = threadIdx.x;
    const int w    = tid >> 5;
    const int lane = tid & 31;
    const int g    = lane >> 2;
    const int tg   = lane & 3;

    // ldmatrix per-lane components
    const int lrow8 = lane & 7;
    const int lhalf = (lane >> 3) & 1;
    const int lquad = lane >> 4;
    const uint32_t swb = smem_u32(sw);
    // A-pattern (Q hi/lo, P): row = w*16 + lhalf*8 + lrow8, col4 = lquad*4
    const uint32_t aoff = ((uint32_t)((w*16 + lhalf*8 + lrow8) * FLD + lquad*4)) * 4;
    const uint32_t qhiA = swb + W_QHI * 4 + aoff;
    const uint32_t qloA = swb + W_QLO * 4 + aoff;
    const uint32_t pA   = swb + W_P   * 4 + aoff;
    // B-pattern (K): per pair u: row = u*16 + lquad*8 + lrow8, col4 = lhalf*4
    uint32_t kA[4];
    #pragma unroll
    for (int u = 0; u < 4; u++)
        kA[u] = swb + (W_K + (u*16 + lquad*8 + lrow8) * FLD + lhalf*4) * 4;

    const float* qbase = g_q + ((size_t)(b*NHEADS + h) * SEQ + qt*FQ) * DEPTH;
    const float* kbase = g_k + (size_t)(b*NHEADS + h) * SEQ * DEPTH;
    const float* vbase = g_v + (size_t)(b*NHEADS + h) * SEQ * DEPTH;

    // stage Q (scaled by 1/8), split into tf32 hi + lo
    #pragma unroll
    for (int i = 0; i < 8; i++) {
        const int idx = tid + i * 256;
        const int r = idx >> 4, c4 = (idx & 15) << 2;
        float4 v = *(const float4*)(qbase + r * DEPTH + c4);
        float xs[4] = {v.x * 0.125f, v.y * 0.125f, v.z * 0.125f, v.w * 0.125f};
        uint4 hi, lo;
        hi.x = f2tf32(xs[0]); lo.x = f2tf32(xs[0] - __uint_as_float(hi.x));
        hi.y = f2tf32(xs[1]); lo.y = f2tf32(xs[1] - __uint_as_float(hi.y));
        hi.z = f2tf32(xs[2]); lo.z = f2tf32(xs[2] - __uint_as_float(hi.z));
        hi.w = f2tf32(xs[3]); lo.w = f2tf32(xs[3] - __uint_as_float(hi.w));
        *(uint4*)(sw + W_QHI + r * FLD + c4) = hi;
        *(uint4*)(sw + W_QLO + r * FLD + c4) = lo;
    }

    // prefetch K/V tile 0 into registers + mask word
    float4 kreg[4], vreg[4];
    #pragma unroll
    for (int j = 0; j < 4; j++) {
        const int slot = tid + j * 256;
        const int r = slot >> 4, c4 = (slot & 15) << 2;
        kreg[j] = *(const float4*)(kbase + (size_t)r * DEPTH + c4);
        vreg[j] = *(const float4*)(vbase + (size_t)r * DEPTH + c4);
    }
    int pmask = (tid < FK) ? mask[b*SEQ + tid] : 0;

    float m0 = -1e30f, m1 = -1e30f, l0 = 0.f, l1 = 0.f;
    float oac[8][4] = {};

    for (int kt = 0; kt < SEQ / FK; kt++) {
        __syncthreads();
        #pragma unroll
        for (int j = 0; j < 4; j++) {
            const int slot = tid + j * 256;
            const int r = slot >> 4, c4 = (slot & 15) << 2;
            uint4 kk = make_uint4(f2tf32(kreg[j].x), f2tf32(kreg[j].y),
                                  f2tf32(kreg[j].z), f2tf32(kreg[j].w));
            uint4 vt = make_uint4(f2tf32(vreg[j].x), f2tf32(vreg[j].y),
                                  f2tf32(vreg[j].z), f2tf32(vreg[j].w));
            *(uint4*)(sw + W_K + r * FLD + c4) = kk;
            *(uint4*)(sw + W_V + r * FLD + c4) = vt;
        }
        if (tid < FK)
            pen[tid] = -1e9f * (float)pmask;
        __syncthreads();

        // prefetch next tile (overlaps with MMAs)
        if (kt + 1 < SEQ / FK) {
            const float* kb2 = kbase + (size_t)(kt + 1) * FK * DEPTH;
            const float* vb2 = vbase + (size_t)(kt + 1) * FK * DEPTH;
            #pragma unroll
            for (int j = 0; j < 4; j++) {
                const int slot = tid + j * 256;
                const int r = slot >> 4, c4 = (slot & 15) << 2;
                kreg[j] = *(const float4*)(kb2 + (size_t)r * DEPTH + c4);
                vreg[j] = *(const float4*)(vb2 + (size_t)r * DEPTH + c4);
            }
            if (tid < FK) pmask = mask[b*SEQ + (kt + 1)*FK + tid];
        }

        // ---- S = Q @ K^T (split-precision, ldmatrix fragments) ----
        float sac[8][4] = {};
        #pragma unroll
        for (int ks = 0; ks < 8; ks++) {
            uint32_t ahi[4], alo[4];
            ldm_x4(ahi, qhiA + ks * 32);
            ldm_x4(alo, qloA + ks * 32);
            #pragma unroll
            for (int u = 0; u < 4; u++) {
                uint32_t kb[4];
                ldm_x4(kb, kA[u] + ks * 32);
                mma_tf32_16x8x8(sac[2*u],     ahi, kb);
                mma_tf32_16x8x8(sac[2*u],     alo, kb);
                mma_tf32_16x8x8(sac[2*u + 1], ahi, kb + 2);
                mma_tf32_16x8x8(sac[2*u + 1], alo, kb + 2);
            }
        }

        // ---- mask + online softmax ----
        #pragma unroll
        for (int nf = 0; nf < 8; nf++) {
            const float2 pe = *(const float2*)&pen[nf*8 + 2*tg];
            sac[nf][0] += pe.x; sac[nf][1] += pe.y;
            sac[nf][2] += pe.x; sac[nf][3] += pe.y;
        }
        float mx0 = -1e30f, mx1 = -1e30f;
        #pragma unroll
        for (int nf = 0; nf < 8; nf++) {
            mx0 = fmaxf(mx0, fmaxf(sac[nf][0], sac[nf][1]));
            mx1 = fmaxf(mx1, fmaxf(sac[nf][2], sac[nf][3]));
        }
        mx0 = fmaxf(mx0, __shfl_xor_sync(0xffffffffu, mx0, 1));
        mx0 = fmaxf(mx0, __shfl_xor_sync(0xffffffffu, mx0, 2));
        mx1 = fmaxf(mx1, __shfl_xor_sync(0xffffffffu, mx1, 1));
        mx1 = fmaxf(mx1, __shfl_xor_sync(0xffffffffu, mx1, 2));
        const float mn0 = fmaxf(m0, mx0), mn1 = fmaxf(m1, mx1);
        const float c0 = __expf(m0 - mn0), c1 = __expf(m1 - mn1);
        float s0 = 0.f, s1 = 0.f;
        #pragma unroll
        for (int nf = 0; nf < 8; nf++) {
            const float e0 = __expf(sac[nf][0] - mn0);
            const float e1 = __expf(sac[nf][1] - mn0);
            const float e2 = __expf(sac[nf][2] - mn1);
            const float e3 = __expf(sac[nf][3] - mn1);
            s0 += e0 + e1; s1 += e2 + e3;
            uint2 r0; r0.x = f2tf32(e0); r0.y = f2tf32(e1);
            uint2 r1; r1.x = f2tf32(e2); r1.y = f2tf32(e3);
            *(uint2*)(sw + W_P + (w*16 + g    ) * FLD + nf*8 + 2*tg) = r0;
            *(uint2*)(sw + W_P + (w*16 + g + 8) * FLD + nf*8 + 2*tg) = r1;
        }
        s0 += __shfl_xor_sync(0xffffffffu, s0, 1);
        s0 += __shfl_xor_sync(0xffffffffu, s0, 2);
        s1 += __shfl_xor_sync(0xffffffffu, s1, 1);
        s1 += __shfl_xor_sync(0xffffffffu, s1, 2);
        l0 = l0 * c0 + s0; l1 = l1 * c1 + s1;
        m0 = mn0; m1 = mn1;
        #pragma unroll
        for (int nf = 0; nf < 8; nf++) {
            oac[nf][0] *= c0; oac[nf][1] *= c0;
            oac[nf][2] *= c1; oac[nf][3] *= c1;
        }
        __syncwarp();   // P stores visible to ldmatrix reads within warp

        // ---- O += P @ V ----
        #pragma unroll
        for (int ks = 0; ks < 8; ks++) {
            uint32_t a[4];
            ldm_x4(a, pA + ks * 32);
            #pragma unroll
            for (int nf = 0; nf < 8; nf++) {
                uint32_t bf[2];
                const uint32_t* vp = sw + W_V + (ks*8 + tg) * FLD + nf*8 + g;
                bf[0] = vp[0]; bf[1] = vp[4*FLD];
                mma_tf32_16x8x8(oac[nf], a, bf);
            }
        }
    }

    // epilogue: merged-head context [B,S,1024]
    const float il0 = 1.0f / l0, il1 = 1.0f / l1;
    const int row0 = qt*FQ + w*16 + g;
    float* ob = g_ctx + ((size_t)b*SEQ + row0) * D_MODEL + h*DEPTH;
    #pragma unroll
    for (int nf = 0; nf < 8; nf++) {
        const int c = nf*8 + 2*tg;
        float2 o0; o0.x = oac[nf][0] * il0; o0.y = oac[nf][1] * il0;
        float2 o1; o1.x = oac[nf][2] * il1; o1.y = oac[nf][3] * il1;
        *(float2*)(ob + c) = o0;
        *(float2*)(ob + (size_t)8 * D_MODEL + c) = o1;
    }
}

// ---------------------------------------------------------------------------
extern "C" void kernel_launch(void* const* d_in, const int* in_sizes, int n_in,
                              void* d_out, int out_size) {
    const float* query = (const float*)d_in[0];
    const float* key   = (const float*)d_in[1];
    const float* value = (const float*)d_in[2];
    const int*   mask  = (const int*)  d_in[3];
    const float* Wq = (const float*)d_in[4];
    const float* bq = (const float*)d_in[5];
    const float* Wk = (const float*)d_in[6];
    const float* bk = (const float*)d_in[7];
    const float* Wv = (const float*)d_in[8];
    const float* bv = (const float*)d_in[9];
    const float* Wo = (const float*)d_in[10];
    const float* bo = (const float*)d_in[11];
    float* out = (float*)d_out;

    cudaFuncSetAttribute(proj_qkv, cudaFuncAttributeMaxDynamicSharedMemorySize, PROJ_SMEM);
    cudaFuncSetAttribute(proj_o,   cudaFuncAttributeMaxDynamicSharedMemorySize, PROJ_SMEM);
    cudaFuncSetAttribute(flash_mma, cudaFuncAttributeMaxDynamicSharedMemorySize, FLASH_SMEM);

    const dim3 gq(D_MODEL / PBN, MTOT / PBM, 3);   // (8, 32, 3)
    proj_qkv<<<gq, 256, PROJ_SMEM>>>(query, key, value, Wq, bq, Wk, bk, Wv, bv);

    flash_mma<<<dim3(SEQ/FQ, NHEADS, BATCH), 256, FLASH_SMEM>>>(mask);

    proj_o<<<dim3(D_MODEL / PBN, MTOT / PBM), 256, PROJ_SMEM>>>(Wo, bo, out);
}

// round 8
// speedup vs baseline: 1.1691x; 1.0492x over previous
#include <cuda_runtime.h>
#include <cstdint>
#include <math.h>

#define D_MODEL 1024
#define NHEADS  16
#define DEPTH   64
#define BATCH   2
#define SEQ     2048
#define MTOT    (BATCH*SEQ)   // 4096

// ---------------- scratch (device globals; no allocations allowed) ----------
__device__ float g_q[BATCH*NHEADS*SEQ*DEPTH];   // 16 MB, [B,H,S,64]
__device__ float g_k[BATCH*NHEADS*SEQ*DEPTH];
__device__ float g_v[BATCH*NHEADS*SEQ*DEPTH];
__device__ float g_ctx[BATCH*SEQ*D_MODEL];      // 16 MB, [B,S,1024]

// ---------------- helpers ----------------------------------------------------
__device__ __forceinline__ uint32_t f2tf32(float x) {
    uint32_t r;
    asm("cvt.rna.tf32.f32 %0, %1;" : "=r"(r) : "f"(x));
    return r;
}
__device__ __forceinline__ void mma_tf32_16x8x8(float* d, const uint32_t* a,
                                                const uint32_t* b) {
    asm volatile(
        "mma.sync.aligned.m16n8k8.row.col.f32.tf32.tf32.f32 "
        "{%0,%1,%2,%3}, {%4,%5,%6,%7}, {%8,%9}, {%0,%1,%2,%3};"
        : "+f"(d[0]), "+f"(d[1]), "+f"(d[2]), "+f"(d[3])
        : "r"(a[0]), "r"(a[1]), "r"(a[2]), "r"(a[3]), "r"(b[0]), "r"(b[1]));
}
__device__ __forceinline__ void ldm_x4(uint32_t* r, uint32_t saddr) {
    asm volatile("ldmatrix.sync.aligned.m8n8.x4.shared.b16 {%0,%1,%2,%3}, [%4];"
        : "=r"(r[0]), "=r"(r[1]), "=r"(r[2]), "=r"(r[3]) : "r"(saddr));
}
__device__ __forceinline__ uint32_t smem_u32(const void* p) {
    uint32_t a;
    asm("{ .reg .u64 t; cvta.to.shared.u64 t, %1; cvt.u32.u64 %0, t; }"
        : "=r"(a) : "l"(p));
    return a;
}
#define CP_ASYNC16(sa, ga) \
    asm volatile("cp.async.ca.shared.global [%0], [%1], 16;" :: "r"(sa), "l"(ga))
#define CP_COMMIT() asm volatile("cp.async.commit_group;" ::: "memory")
#define CP_WAIT(n)  asm volatile("cp.async.wait_group %0;" :: "n"(n) : "memory")

// ============ tf32 tensor-core projection (cp.async pipelined) ==============
constexpr int PBM = 128, PBN = 128, PBK = 32, PLD = PBK + 4;   // PLD=36
constexpr int PROJ_STAGE = PBM * PLD;                           // floats
constexpr int PROJ_SMEM  = 4 * PROJ_STAGE * 4;                  // 73728 bytes

template<int SPLIT>
__device__ __forceinline__
void proj_body(float* smf, const float* __restrict__ A, const float* __restrict__ W,
               const float* __restrict__ bias, float* __restrict__ out) {
    const int tid  = threadIdx.x;
    const int wid  = tid >> 5;
    const int lane = tid & 31;
    const int g    = lane >> 2;
    const int tg   = lane & 3;
    const int wm   = wid >> 2;
    const int wn   = wid & 3;
    const int bm   = blockIdx.y * PBM;
    const int bn   = blockIdx.x * PBN;

    const int lrow8 = lane & 7;
    const int lhalf = (lane >> 3) & 1;
    const int lquad = lane >> 4;

    float* As0 = smf;
    float* Bs0 = smf + 2 * PROJ_STAGE;
    const uint32_t smb = smem_u32(smf);

    uint32_t aAddr[4], bAddr[2];
    #pragma unroll
    for (int mi = 0; mi < 4; mi++)
        aAddr[mi] = smb + ((wm*64 + mi*16 + lhalf*8 + lrow8) * PLD + lquad*4) * 4;
    #pragma unroll
    for (int u = 0; u < 2; u++)
        bAddr[u] = smb + (2*PROJ_STAGE + (wn*32 + (2*u + lquad)*8 + lrow8) * PLD + lhalf*4) * 4;

    float acc[4][4][4] = {};

    auto issue = [&](int s) {
        const int buf = s & 1;
        const int k0  = s * PBK;
        float* As = As0 + buf * PROJ_STAGE;
        float* Bs = Bs0 + buf * PROJ_STAGE;
        #pragma unroll
        for (int i = 0; i < 4; i++) {
            const int idx = tid + i * 256;
            const int r = idx >> 3;
            const int c = (idx & 7) * 4;
            CP_ASYNC16(smem_u32(&As[r * PLD + c]), A + (size_t)(bm + r) * D_MODEL + k0 + c);
            CP_ASYNC16(smem_u32(&Bs[r * PLD + c]), W + (size_t)(bn + r) * D_MODEL + k0 + c);
        }
        CP_COMMIT();
    };

    issue(0);
    for (int s = 0; s < D_MODEL / PBK; s++) {
        const uint32_t bufo = (uint32_t)(s & 1) * PROJ_STAGE * 4;
        if (s + 1 < D_MODEL / PBK) { issue(s + 1); CP_WAIT(1); }
        else                       { CP_WAIT(0); }
        __syncthreads();

        #pragma unroll
        for (int ks = 0; ks < PBK; ks += 8) {
            uint32_t araw[4][4], braw[2][4];
            #pragma unroll
            for (int mi = 0; mi < 4; mi++) ldm_x4(araw[mi], aAddr[mi] + bufo + ks*4);
            #pragma unroll
            for (int u = 0; u < 2; u++)    ldm_x4(braw[u],  bAddr[u]  + bufo + ks*4);

            uint32_t afr[4][4], bfr[4][2];
            #pragma unroll
            for (int mi = 0; mi < 4; mi++)
                #pragma unroll
                for (int e = 0; e < 4; e++)
                    afr[mi][e] = f2tf32(__uint_as_float(araw[mi][e]));
            #pragma unroll
            for (int u = 0; u < 2; u++) {
                bfr[2*u  ][0] = f2tf32(__uint_as_float(braw[u][0]));
                bfr[2*u  ][1] = f2tf32(__uint_as_float(braw[u][1]));
                bfr[2*u+1][0] = f2tf32(__uint_as_float(braw[u][2]));
                bfr[2*u+1][1] = f2tf32(__uint_as_float(braw[u][3]));
            }
            #pragma unroll
            for (int mi = 0; mi < 4; mi++)
                #pragma unroll
                for (int ni = 0; ni < 4; ni++)
                    mma_tf32_16x8x8(acc[mi][ni], afr[mi], bfr[ni]);
        }
        __syncthreads();
    }

    #pragma unroll
    for (int mi = 0; mi < 4; mi++) {
        #pragma unroll
        for (int ni = 0; ni < 4; ni++) {
            const int col = bn + wn * 32 + ni * 8 + tg * 2;
            const float2 bv = *(const float2*)(bias + col);
            #pragma unroll
            for (int half = 0; half < 2; half++) {
                const int m = bm + wm * 64 + mi * 16 + g + half * 8;
                float2 o;
                o.x = acc[mi][ni][half * 2 + 0] + bv.x;
                o.y = acc[mi][ni][half * 2 + 1] + bv.y;
                if (SPLIT) {
                    const int b = m >> 11, sq = m & 2047;
                    const int h = col >> 6, d = col & 63;
                    *(float2*)(out + (((size_t)(b * NHEADS + h) * SEQ) + sq) * DEPTH + d) = o;
                } else {
                    *(float2*)(out + (size_t)m * D_MODEL + col) = o;
                }
            }
        }
    }
}

__global__ __launch_bounds__(256)
void proj_qkv(const float* __restrict__ q, const float* __restrict__ k,
              const float* __restrict__ v,
              const float* __restrict__ Wq, const float* __restrict__ bq,
              const float* __restrict__ Wk, const float* __restrict__ bk,
              const float* __restrict__ Wv, const float* __restrict__ bv) {
    extern __shared__ float smf[];
    const float *A, *W, *bias;
    float* out;
    if (blockIdx.z == 0)      { A = q; W = Wq; bias = bq; out = g_q; }
    else if (blockIdx.z == 1) { A = k; W = Wk; bias = bk; out = g_k; }
    else                      { A = v; W = Wv; bias = bv; out = g_v; }
    proj_body<1>(smf, A, W, bias, out);
}

__global__ __launch_bounds__(256)
void proj_o(const float* __restrict__ W, const float* __restrict__ bias,
            float* __restrict__ out) {
    extern __shared__ float smf[];
    proj_body<0>(smf, g_ctx, W, bias, out);
}

// ================= tensor-core flash attention v6 ============================
// Q stored RAW fp32 (single buffer); hi/lo tf32 split computed at fragment
// load. Smem 104.9KB -> 2 CTAs/SM (16 warps).
constexpr int FQ  = 128;
constexpr int FK  = 64;
constexpr int FLD = 68;

constexpr int W_QRAW = 0;
constexpr int W_K    = W_QRAW + FQ * FLD;   // 8704
constexpr int W_V    = W_K    + FK * FLD;   // 13056
constexpr int W_P    = W_V    + FK * FLD;   // 17408
constexpr int W_PEN  = W_P    + FQ * FLD;   // 26112
constexpr int FLASH_SMEM = (W_PEN + FK) * 4;   // 104704 bytes

__global__ __launch_bounds__(256, 2)
void flash_mma(const int* __restrict__ mask) {
    extern __shared__ uint32_t sw[];
    float* pen = (float*)(sw + W_PEN);

    const int qt = blockIdx.x, h = blockIdx.y, b = blockIdx.z;
    const int tid  = threadIdx.x;
    const int w    = tid >> 5;
    const int lane = tid & 31;
    const int g    = lane >> 2;
    const int tg   = lane & 3;

    const int lrow8 = lane & 7;
    const int lhalf = (lane >> 3) & 1;
    const int lquad = lane >> 4;
    const uint32_t swb = smem_u32(sw);
    const uint32_t aoff = ((uint32_t)((w*16 + lhalf*8 + lrow8) * FLD + lquad*4)) * 4;
    const uint32_t qA = swb + W_QRAW * 4 + aoff;
    const uint32_t pA = swb + W_P    * 4 + aoff;
    uint32_t kA[4];
    #pragma unroll
    for (int u = 0; u < 4; u++)
        kA[u] = swb + (W_K + (u*16 + lquad*8 + lrow8) * FLD + lhalf*4) * 4;

    const float* qbase = g_q + ((size_t)(b*NHEADS + h) * SEQ + qt*FQ) * DEPTH;
    const float* kbase = g_k + (size_t)(b*NHEADS + h) * SEQ * DEPTH;
    const float* vbase = g_v + (size_t)(b*NHEADS + h) * SEQ * DEPTH;

    // stage Q raw (scaled by 1/8)
    #pragma unroll
    for (int i = 0; i < 8; i++) {
        const int idx = tid + i * 256;
        const int r = idx >> 4, c4 = (idx & 15) << 2;
        float4 v = *(const float4*)(qbase + r * DEPTH + c4);
        v.x *= 0.125f; v.y *= 0.125f; v.z *= 0.125f; v.w *= 0.125f;
        *(float4*)((float*)sw + W_QRAW + r * FLD + c4) = v;
    }

    // prefetch K/V tile 0 into registers + mask word
    float4 kreg[4], vreg[4];
    #pragma unroll
    for (int j = 0; j < 4; j++) {
        const int slot = tid + j * 256;
        const int r = slot >> 4, c4 = (slot & 15) << 2;
        kreg[j] = *(const float4*)(kbase + (size_t)r * DEPTH + c4);
        vreg[j] = *(const float4*)(vbase + (size_t)r * DEPTH + c4);
    }
    int pmask = (tid < FK) ? mask[b*SEQ + tid] : 0;

    float m0 = -1e30f, m1 = -1e30f, l0 = 0.f, l1 = 0.f;
    float oac[8][4] = {};

    for (int kt = 0; kt < SEQ / FK; kt++) {
        __syncthreads();
        #pragma unroll
        for (int j = 0; j < 4; j++) {
            const int slot = tid + j * 256;
            const int r = slot >> 4, c4 = (slot & 15) << 2;
            uint4 kk = make_uint4(f2tf32(kreg[j].x), f2tf32(kreg[j].y),
                                  f2tf32(kreg[j].z), f2tf32(kreg[j].w));
            uint4 vt = make_uint4(f2tf32(vreg[j].x), f2tf32(vreg[j].y),
                                  f2tf32(vreg[j].z), f2tf32(vreg[j].w));
            *(uint4*)(sw + W_K + r * FLD + c4) = kk;
            *(uint4*)(sw + W_V + r * FLD + c4) = vt;
        }
        if (tid < FK)
            pen[tid] = -1e9f * (float)pmask;
        __syncthreads();

        // prefetch next tile (overlaps with MMAs)
        if (kt + 1 < SEQ / FK) {
            const float* kb2 = kbase + (size_t)(kt + 1) * FK * DEPTH;
            const float* vb2 = vbase + (size_t)(kt + 1) * FK * DEPTH;
            #pragma unroll
            for (int j = 0; j < 4; j++) {
                const int slot = tid + j * 256;
                const int r = slot >> 4, c4 = (slot & 15) << 2;
                kreg[j] = *(const float4*)(kb2 + (size_t)r * DEPTH + c4);
                vreg[j] = *(const float4*)(vb2 + (size_t)r * DEPTH + c4);
            }
            if (tid < FK) pmask = mask[b*SEQ + (kt + 1)*FK + tid];
        }

        // ---- S = Q @ K^T (split-precision; hi/lo derived from raw Q) ----
        float sac[8][4] = {};
        #pragma unroll
        for (int ks = 0; ks < 8; ks++) {
            uint32_t qraw[4], ahi[4], alo[4];
            ldm_x4(qraw, qA + ks * 32);
            #pragma unroll
            for (int e = 0; e < 4; e++) {
                const float f = __uint_as_float(qraw[e]);
                ahi[e] = f2tf32(f);
                alo[e] = f2tf32(f - __uint_as_float(ahi[e]));
            }
            #pragma unroll
            for (int u = 0; u < 4; u++) {
                uint32_t kb[4];
                ldm_x4(kb, kA[u] + ks * 32);
                mma_tf32_16x8x8(sac[2*u],     ahi, kb);
                mma_tf32_16x8x8(sac[2*u],     alo, kb);
                mma_tf32_16x8x8(sac[2*u + 1], ahi, kb + 2);
                mma_tf32_16x8x8(sac[2*u + 1], alo, kb + 2);
            }
        }

        // ---- mask + online softmax ----
        #pragma unroll
        for (int nf = 0; nf < 8; nf++) {
            const float2 pe = *(const float2*)&pen[nf*8 + 2*tg];
            sac[nf][0] += pe.x; sac[nf][1] += pe.y;
            sac[nf][2] += pe.x; sac[nf][3] += pe.y;
        }
        float mx0 = -1e30f, mx1 = -1e30f;
        #pragma unroll
        for (int nf = 0; nf < 8; nf++) {
            mx0 = fmaxf(mx0, fmaxf(sac[nf][0], sac[nf][1]));
            mx1 = fmaxf(mx1, fmaxf(sac[nf][2], sac[nf][3]));
        }
        mx0 = fmaxf(mx0, __shfl_xor_sync(0xffffffffu, mx0, 1));
        mx0 = fmaxf(mx0, __shfl_xor_sync(0xffffffffu, mx0, 2));
        mx1 = fmaxf(mx1, __shfl_xor_sync(0xffffffffu, mx1, 1));
        mx1 = fmaxf(mx1, __shfl_xor_sync(0xffffffffu, mx1, 2));
        const float mn0 = fmaxf(m0, mx0), mn1 = fmaxf(m1, mx1);
        const float c0 = __expf(m0 - mn0), c1 = __expf(m1 - mn1);
        float s0 = 0.f, s1 = 0.f;
        #pragma unroll
        for (int nf = 0; nf < 8; nf++) {
            const float e0 = __expf(sac[nf][0] - mn0);
            const float e1 = __expf(sac[nf][1] - mn0);
            const float e2 = __expf(sac[nf][2] - mn1);
            const float e3 = __expf(sac[nf][3] - mn1);
            s0 += e0 + e1; s1 += e2 + e3;
            uint2 r0; r0.x = f2tf32(e0); r0.y = f2tf32(e1);
            uint2 r1; r1.x = f2tf32(e2); r1.y = f2tf32(e3);
            *(uint2*)(sw + W_P + (w*16 + g    ) * FLD + nf*8 + 2*tg) = r0;
            *(uint2*)(sw + W_P + (w*16 + g + 8) * FLD + nf*8 + 2*tg) = r1;
        }
        s0 += __shfl_xor_sync(0xffffffffu, s0, 1);
        s0 += __shfl_xor_sync(0xffffffffu, s0, 2);
        s1 += __shfl_xor_sync(0xffffffffu, s1, 1);
        s1 += __shfl_xor_sync(0xffffffffu, s1, 2);
        l0 = l0 * c0 + s0; l1 = l1 * c1 + s1;
        m0 = mn0; m1 = mn1;
        #pragma unroll
        for (int nf = 0; nf < 8; nf++) {
            oac[nf][0] *= c0; oac[nf][1] *= c0;
            oac[nf][2] *= c1; oac[nf][3] *= c1;
        }
        __syncwarp();   // P stores visible to ldmatrix reads within warp

        // ---- O += P @ V ----
        #pragma unroll
        for (int ks = 0; ks < 8; ks++) {
            uint32_t a[4];
            ldm_x4(a, pA + ks * 32);
            #pragma unroll
            for (int nf = 0; nf < 8; nf++) {
                uint32_t bf[2];
                const uint32_t* vp = sw + W_V + (ks*8 + tg) * FLD + nf*8 + g;
                bf[0] = vp[0]; bf[1] = vp[4*FLD];
                mma_tf32_16x8x8(oac[nf], a, bf);
            }
        }
    }

    // epilogue: merged-head context [B,S,1024]
    const float il0 = 1.0f / l0, il1 = 1.0f / l1;
    const int row0 = qt*FQ + w*16 + g;
    float* ob = g_ctx + ((size_t)b*SEQ + row0) * D_MODEL + h*DEPTH;
    #pragma unroll
    for (int nf = 0; nf < 8; nf++) {
        const int c = nf*8 + 2*tg;
        float2 o0; o0.x = oac[nf][0] * il0; o0.y = oac[nf][1] * il0;
        float2 o1; o1.x = oac[nf][2] * il1; o1.y = oac[nf][3] * il1;
        *(float2*)(ob + c) = o0;
        *(float2*)(ob + (size_t)8 * D_MODEL + c) = o1;
    }
}

// ---------------------------------------------------------------------------
extern "C" void kernel_launch(void* const* d_in, const int* in_sizes, int n_in,
                              void* d_out, int out_size) {
    const float* query = (const float*)d_in[0];
    const float* key   = (const float*)d_in[1];
    const float* value = (const float*)d_in[2];
    const int*   mask  = (const int*)  d_in[3];
    const float* Wq = (const float*)d_in[4];
    const float* bq = (const float*)d_in[5];
    const float* Wk = (const float*)d_in[6];
    const float* bk = (const float*)d_in[7];
    const float* Wv = (const float*)d_in[8];
    const float* bv = (const float*)d_in[9];
    const float* Wo = (const float*)d_in[10];
    const float* bo = (const float*)d_in[11];
    float* out = (float*)d_out;

    cudaFuncSetAttribute(proj_qkv, cudaFuncAttributeMaxDynamicSharedMemorySize, PROJ_SMEM);
    cudaFuncSetAttribute(proj_o,   cudaFuncAttributeMaxDynamicSharedMemorySize, PROJ_SMEM);
    cudaFuncSetAttribute(flash_mma, cudaFuncAttributeMaxDynamicSharedMemorySize, FLASH_SMEM);

    const dim3 gq(D_MODEL / PBN, MTOT / PBM, 3);   // (8, 32, 3)
    proj_qkv<<<gq, 256, PROJ_SMEM>>>(query, key, value, Wq, bq, Wk, bk, Wv, bv);

    flash_mma<<<dim3(SEQ/FQ, NHEADS, BATCH), 256, FLASH_SMEM>>>(mask);

    proj_o<<<dim3(D_MODEL / PBN, MTOT / PBM), 256, PROJ_SMEM>>>(Wo, bo, out);
}

// round 9
// speedup vs baseline: 1.3115x; 1.1218x over previous
#include <cuda_runtime.h>
#include <cuda_bf16.h>
#include <cstdint>
#include <math.h>

#define D_MODEL 1024
#define NHEADS  16
#define DEPTH   64
#define BATCH   2
#define SEQ     2048
#define MTOT    (BATCH*SEQ)   // 4096

// ---------------- scratch (device globals; no allocations allowed) ----------
__device__ float g_q[BATCH*NHEADS*SEQ*DEPTH];   // 16 MB, [B,H,S,64]
__device__ float g_k[BATCH*NHEADS*SEQ*DEPTH];
__device__ float g_v[BATCH*NHEADS*SEQ*DEPTH];
__device__ float g_ctx[BATCH*SEQ*D_MODEL];      // 16 MB, [B,S,1024]

// ---------------- helpers ----------------------------------------------------
__device__ __forceinline__ uint32_t f2tf32(float x) {
    uint32_t r;
    asm("cvt.rna.tf32.f32 %0, %1;" : "=r"(r) : "f"(x));
    return r;
}
__device__ __forceinline__ void mma_tf32_16x8x8(float* d, const uint32_t* a,
                                                const uint32_t* b) {
    asm volatile(
        "mma.sync.aligned.m16n8k8.row.col.f32.tf32.tf32.f32 "
        "{%0,%1,%2,%3}, {%4,%5,%6,%7}, {%8,%9}, {%0,%1,%2,%3};"
        : "+f"(d[0]), "+f"(d[1]), "+f"(d[2]), "+f"(d[3])
        : "r"(a[0]), "r"(a[1]), "r"(a[2]), "r"(a[3]), "r"(b[0]), "r"(b[1]));
}
__device__ __forceinline__ void mma_bf16_16x8x16(float* d, const uint32_t* a,
                                                 const uint32_t* b) {
    asm volatile(
        "mma.sync.aligned.m16n8k16.row.col.f32.bf16.bf16.f32 "
        "{%0,%1,%2,%3}, {%4,%5,%6,%7}, {%8,%9}, {%0,%1,%2,%3};"
        : "+f"(d[0]), "+f"(d[1]), "+f"(d[2]), "+f"(d[3])
        : "r"(a[0]), "r"(a[1]), "r"(a[2]), "r"(a[3]), "r"(b[0]), "r"(b[1]));
}
__device__ __forceinline__ void ldm_x4(uint32_t* r, uint32_t saddr) {
    asm volatile("ldmatrix.sync.aligned.m8n8.x4.shared.b16 {%0,%1,%2,%3}, [%4];"
        : "=r"(r[0]), "=r"(r[1]), "=r"(r[2]), "=r"(r[3]) : "r"(saddr));
}
__device__ __forceinline__ void ldm_x4_t(uint32_t* r, uint32_t saddr) {
    asm volatile("ldmatrix.sync.aligned.m8n8.x4.trans.shared.b16 {%0,%1,%2,%3}, [%4];"
        : "=r"(r[0]), "=r"(r[1]), "=r"(r[2]), "=r"(r[3]) : "r"(saddr));
}
__device__ __forceinline__ uint32_t smem_u32(const void* p) {
    uint32_t a;
    asm("{ .reg .u64 t; cvta.to.shared.u64 t, %1; cvt.u32.u64 %0, t; }"
        : "=r"(a) : "l"(p));
    return a;
}
// pack two floats into bf16x2 (a -> low half, b -> high half), plus residual pack
__device__ __forceinline__ uint32_t bf2pack(float a, float b) {
    uint32_t p;
    asm("cvt.rn.bf16x2.f32 %0, %1, %2;" : "=r"(p) : "f"(b), "f"(a));
    return p;
}
__device__ __forceinline__ void split_pack(float a, float b, uint32_t& hi, uint32_t& lo) {
    hi = bf2pack(a, b);
    const float fa = __uint_as_float(hi << 16);
    const float fb = __uint_as_float(hi & 0xffff0000u);
    lo = bf2pack(a - fa, b - fb);
}
#define CP_ASYNC16(sa, ga) \
    asm volatile("cp.async.ca.shared.global [%0], [%1], 16;" :: "r"(sa), "l"(ga))
#define CP_COMMIT() asm volatile("cp.async.commit_group;" ::: "memory")
#define CP_WAIT(n)  asm volatile("cp.async.wait_group %0;" :: "n"(n) : "memory")

// ============ tf32 tensor-core projection (cp.async pipelined) ==============
constexpr int PBM = 128, PBN = 128, PBK = 32, PLD = PBK + 4;   // PLD=36
constexpr int PROJ_STAGE = PBM * PLD;                           // floats
constexpr int PROJ_SMEM  = 4 * PROJ_STAGE * 4;                  // 73728 bytes

template<int SPLIT>
__device__ __forceinline__
void proj_body(float* smf, const float* __restrict__ A, const float* __restrict__ W,
               const float* __restrict__ bias, float* __restrict__ out) {
    const int tid  = threadIdx.x;
    const int wid  = tid >> 5;
    const int lane = tid & 31;
    const int g    = lane >> 2;
    const int tg   = lane & 3;
    const int wm   = wid >> 2;
    const int wn   = wid & 3;
    const int bm   = blockIdx.y * PBM;
    const int bn   = blockIdx.x * PBN;

    const int lrow8 = lane & 7;
    const int lhalf = (lane >> 3) & 1;
    const int lquad = lane >> 4;

    float* As0 = smf;
    float* Bs0 = smf + 2 * PROJ_STAGE;
    const uint32_t smb = smem_u32(smf);

    uint32_t aAddr[4], bAddr[2];
    #pragma unroll
    for (int mi = 0; mi < 4; mi++)
        aAddr[mi] = smb + ((wm*64 + mi*16 + lhalf*8 + lrow8) * PLD + lquad*4) * 4;
    #pragma unroll
    for (int u = 0; u < 2; u++)
        bAddr[u] = smb + (2*PROJ_STAGE + (wn*32 + (2*u + lquad)*8 + lrow8) * PLD + lhalf*4) * 4;

    float acc[4][4][4] = {};

    auto issue = [&](int s) {
        const int buf = s & 1;
        const int k0  = s * PBK;
        float* As = As0 + buf * PROJ_STAGE;
        float* Bs = Bs0 + buf * PROJ_STAGE;
        #pragma unroll
        for (int i = 0; i < 4; i++) {
            const int idx = tid + i * 256;
            const int r = idx >> 3;
            const int c = (idx & 7) * 4;
            CP_ASYNC16(smem_u32(&As[r * PLD + c]), A + (size_t)(bm + r) * D_MODEL + k0 + c);
            CP_ASYNC16(smem_u32(&Bs[r * PLD + c]), W + (size_t)(bn + r) * D_MODEL + k0 + c);
        }
        CP_COMMIT();
    };

    issue(0);
    for (int s = 0; s < D_MODEL / PBK; s++) {
        const uint32_t bufo = (uint32_t)(s & 1) * PROJ_STAGE * 4;
        if (s + 1 < D_MODEL / PBK) { issue(s + 1); CP_WAIT(1); }
        else                       { CP_WAIT(0); }
        __syncthreads();

        #pragma unroll
        for (int ks = 0; ks < PBK; ks += 8) {
            uint32_t araw[4][4], braw[2][4];
            #pragma unroll
            for (int mi = 0; mi < 4; mi++) ldm_x4(araw[mi], aAddr[mi] + bufo + ks*4);
            #pragma unroll
            for (int u = 0; u < 2; u++)    ldm_x4(braw[u],  bAddr[u]  + bufo + ks*4);

            uint32_t afr[4][4], bfr[4][2];
            #pragma unroll
            for (int mi = 0; mi < 4; mi++)
                #pragma unroll
                for (int e = 0; e < 4; e++)
                    afr[mi][e] = f2tf32(__uint_as_float(araw[mi][e]));
            #pragma unroll
            for (int u = 0; u < 2; u++) {
                bfr[2*u  ][0] = f2tf32(__uint_as_float(braw[u][0]));
                bfr[2*u  ][1] = f2tf32(__uint_as_float(braw[u][1]));
                bfr[2*u+1][0] = f2tf32(__uint_as_float(braw[u][2]));
                bfr[2*u+1][1] = f2tf32(__uint_as_float(braw[u][3]));
            }
            #pragma unroll
            for (int mi = 0; mi < 4; mi++)
                #pragma unroll
                for (int ni = 0; ni < 4; ni++)
                    mma_tf32_16x8x8(acc[mi][ni], afr[mi], bfr[ni]);
        }
        __syncthreads();
    }

    #pragma unroll
    for (int mi = 0; mi < 4; mi++) {
        #pragma unroll
        for (int ni = 0; ni < 4; ni++) {
            const int col = bn + wn * 32 + ni * 8 + tg * 2;
            const float2 bv = *(const float2*)(bias + col);
            #pragma unroll
            for (int half = 0; half < 2; half++) {
                const int m = bm + wm * 64 + mi * 16 + g + half * 8;
                float2 o;
                o.x = acc[mi][ni][half * 2 + 0] + bv.x;
                o.y = acc[mi][ni][half * 2 + 1] + bv.y;
                if (SPLIT) {
                    const int b = m >> 11, sq = m & 2047;
                    const int h = col >> 6, d = col & 63;
                    *(float2*)(out + (((size_t)(b * NHEADS + h) * SEQ) + sq) * DEPTH + d) = o;
                } else {
                    *(float2*)(out + (size_t)m * D_MODEL + col) = o;
                }
            }
        }
    }
}

__global__ __launch_bounds__(256)
void proj_qkv(const float* __restrict__ q, const float* __restrict__ k,
              const float* __restrict__ v,
              const float* __restrict__ Wq, const float* __restrict__ bq,
              const float* __restrict__ Wk, const float* __restrict__ bk,
              const float* __restrict__ Wv, const float* __restrict__ bv) {
    extern __shared__ float smf[];
    const float *A, *W, *bias;
    float* out;
    if (blockIdx.z == 0)      { A = q; W = Wq; bias = bq; out = g_q; }
    else if (blockIdx.z == 1) { A = k; W = Wk; bias = bk; out = g_k; }
    else                      { A = v; W = Wv; bias = bv; out = g_v; }
    proj_body<1>(smf, A, W, bias, out);
}

__global__ __launch_bounds__(256)
void proj_o(const float* __restrict__ W, const float* __restrict__ bias,
            float* __restrict__ out) {
    extern __shared__ float smf[];
    proj_body<0>(smf, g_ctx, W, bias, out);
}

// ================= flash attention v7: split-bf16 3-MMA ======================
// All operands hi+lo bf16 (x = xh + xl). QK^T and P@V computed as
// ah@bh + al@bh + ah@bl (error ~2^-17). m16n8k16 bf16 MMAs, ldmatrix b16
// fragments (trans for V). Row stride 72 bf16 (144B -> conflict-free ldmatrix).
constexpr int FQ  = 128;
constexpr int FK  = 64;
constexpr int FL  = 72;                       // row stride in bf16 units

constexpr int W_QH = 0;                       // 128*72
constexpr int W_QL = W_QH + FQ * FL;          // 9216
constexpr int W_KH = W_QL + FQ * FL;          // 18432
constexpr int W_KL = W_KH + FK * FL;          // 23040
constexpr int W_VH = W_KL + FK * FL;          // 27648
constexpr int W_VL = W_VH + FK * FL;          // 32256
constexpr int W_PH = W_VL + FK * FL;          // 36864
constexpr int W_PL = W_PH + FQ * FL;          // 46080
constexpr int SM_END = W_PL + FQ * FL;        // 55296 bf16 units
constexpr int PEN_B  = SM_END * 2;            // byte offset of pen
constexpr int FLASH_SMEM = PEN_B + FK * 4;    // 110848 bytes

// byte deltas hi->lo buffers
constexpr uint32_t QLOFF = (W_QL - W_QH) * 2;
constexpr uint32_t KLOFF = (W_KL - W_KH) * 2;
constexpr uint32_t VLOFF = (W_VL - W_VH) * 2;
constexpr uint32_t PLOFF = (W_PL - W_PH) * 2;

__global__ __launch_bounds__(256, 2)
void flash_mma(const int* __restrict__ mask) {
    extern __shared__ uint32_t sw[];
    uint16_t* sb = (uint16_t*)sw;
    float* pen = (float*)((char*)sw + PEN_B);

    const int qt = blockIdx.x, h = blockIdx.y, b = blockIdx.z;
    const int tid  = threadIdx.x;
    const int w    = tid >> 5;
    const int lane = tid & 31;
    const int g    = lane >> 2;
    const int tg   = lane & 3;

    const uint32_t swb = smem_u32(sw);
    // A-pattern (Q, P): row = w*16 + (lane&15), col8 = (lane>>4)*8
    const uint32_t arow = w*16 + (lane & 15);
    const uint32_t acol = (lane >> 4) * 8;
    const uint32_t qA = swb + (W_QH + arow * FL + acol) * 2;
    const uint32_t pA = swb + (W_PH + arow * FL + acol) * 2;
    // K B-pattern (non-trans): row = u*16 + (lane>>4)*8 + (lane&7), col8 = ((lane>>3)&1)*8
    uint32_t kA[4];
    #pragma unroll
    for (int u = 0; u < 4; u++)
        kA[u] = swb + (W_KH + (u*16 + (lane >> 4) * 8 + (lane & 7)) * FL
                       + ((lane >> 3) & 1) * 8) * 2;
    // V B-pattern (trans): row = ((lane>>3)&1)*8 + (lane&7) (+ks*16), col = u*16 + (lane>>4)*8
    uint32_t vA[4];
    #pragma unroll
    for (int u = 0; u < 4; u++)
        vA[u] = swb + (W_VH + (((lane >> 3) & 1) * 8 + (lane & 7)) * FL
                       + u*16 + (lane >> 4) * 8) * 2;

    const float* qbase = g_q + ((size_t)(b*NHEADS + h) * SEQ + qt*FQ) * DEPTH;
    const float* kbase = g_k + (size_t)(b*NHEADS + h) * SEQ * DEPTH;
    const float* vbase = g_v + (size_t)(b*NHEADS + h) * SEQ * DEPTH;

    // stage Q (scaled by 1/8), split bf16 hi/lo
    #pragma unroll
    for (int i = 0; i < 8; i++) {
        const int idx = tid + i * 256;
        const int r = idx >> 4, c4 = (idx & 15) << 2;
        float4 v = *(const float4*)(qbase + r * DEPTH + c4);
        v.x *= 0.125f; v.y *= 0.125f; v.z *= 0.125f; v.w *= 0.125f;
        uint2 hi, lo;
        split_pack(v.x, v.y, hi.x, lo.x);
        split_pack(v.z, v.w, hi.y, lo.y);
        *(uint2*)(sb + W_QH + r * FL + c4) = hi;
        *(uint2*)(sb + W_QL + r * FL + c4) = lo;
    }

    // prefetch K/V tile 0 + mask word
    float4 kreg[4], vreg[4];
    #pragma unroll
    for (int j = 0; j < 4; j++) {
        const int slot = tid + j * 256;
        const int r = slot >> 4, c4 = (slot & 15) << 2;
        kreg[j] = *(const float4*)(kbase + (size_t)r * DEPTH + c4);
        vreg[j] = *(const float4*)(vbase + (size_t)r * DEPTH + c4);
    }
    int pmask = (tid < FK) ? mask[b*SEQ + tid] : 0;

    float m0 = -1e30f, m1 = -1e30f, l0 = 0.f, l1 = 0.f;
    float oac[8][4] = {};

    for (int kt = 0; kt < SEQ / FK; kt++) {
        __syncthreads();
        #pragma unroll
        for (int j = 0; j < 4; j++) {
            const int slot = tid + j * 256;
            const int r = slot >> 4, c4 = (slot & 15) << 2;
            uint2 khi, klo, vhi, vlo;
            split_pack(kreg[j].x, kreg[j].y, khi.x, klo.x);
            split_pack(kreg[j].z, kreg[j].w, khi.y, klo.y);
            split_pack(vreg[j].x, vreg[j].y, vhi.x, vlo.x);
            split_pack(vreg[j].z, vreg[j].w, vhi.y, vlo.y);
            *(uint2*)(sb + W_KH + r * FL + c4) = khi;
            *(uint2*)(sb + W_KL + r * FL + c4) = klo;
            *(uint2*)(sb + W_VH + r * FL + c4) = vhi;
            *(uint2*)(sb + W_VL + r * FL + c4) = vlo;
        }
        if (tid < FK)
            pen[tid] = -1e9f * (float)pmask;
        __syncthreads();

        // prefetch next tile (overlaps with MMAs)
        if (kt + 1 < SEQ / FK) {
            const float* kb2 = kbase + (size_t)(kt + 1) * FK * DEPTH;
            const float* vb2 = vbase + (size_t)(kt + 1) * FK * DEPTH;
            #pragma unroll
            for (int j = 0; j < 4; j++) {
                const int slot = tid + j * 256;
                const int r = slot >> 4, c4 = (slot & 15) << 2;
                kreg[j] = *(const float4*)(kb2 + (size_t)r * DEPTH + c4);
                vreg[j] = *(const float4*)(vb2 + (size_t)r * DEPTH + c4);
            }
            if (tid < FK) pmask = mask[b*SEQ + (kt + 1)*FK + tid];
        }

        // ---- S = Q @ K^T : qh@kh + ql@kh + qh@kl ----
        float sac[8][4] = {};
        #pragma unroll
        for (int ks = 0; ks < 4; ks++) {
            uint32_t qh[4], ql[4];
            ldm_x4(qh, qA + ks * 32);
            ldm_x4(ql, qA + ks * 32 + QLOFF);
            #pragma unroll
            for (int u = 0; u < 4; u++) {
                uint32_t kh[4], kl[4];
                ldm_x4(kh, kA[u] + ks * 32);
                ldm_x4(kl, kA[u] + ks * 32 + KLOFF);
                mma_bf16_16x8x16(sac[2*u],     qh, kh);
                mma_bf16_16x8x16(sac[2*u],     ql, kh);
                mma_bf16_16x8x16(sac[2*u],     qh, kl);
                mma_bf16_16x8x16(sac[2*u + 1], qh, kh + 2);
                mma_bf16_16x8x16(sac[2*u + 1], ql, kh + 2);
                mma_bf16_16x8x16(sac[2*u + 1], qh, kl + 2);
            }
        }

        // ---- mask + online softmax ----
        #pragma unroll
        for (int nf = 0; nf < 8; nf++) {
            const float2 pe = *(const float2*)&pen[nf*8 + 2*tg];
            sac[nf][0] += pe.x; sac[nf][1] += pe.y;
            sac[nf][2] += pe.x; sac[nf][3] += pe.y;
        }
        float mx0 = -1e30f, mx1 = -1e30f;
        #pragma unroll
        for (int nf = 0; nf < 8; nf++) {
            mx0 = fmaxf(mx0, fmaxf(sac[nf][0], sac[nf][1]));
            mx1 = fmaxf(mx1, fmaxf(sac[nf][2], sac[nf][3]));
        }
        mx0 = fmaxf(mx0, __shfl_xor_sync(0xffffffffu, mx0, 1));
        mx0 = fmaxf(mx0, __shfl_xor_sync(0xffffffffu, mx0, 2));
        mx1 = fmaxf(mx1, __shfl_xor_sync(0xffffffffu, mx1, 1));
        mx1 = fmaxf(mx1, __shfl_xor_sync(0xffffffffu, mx1, 2));
        const float mn0 = fmaxf(m0, mx0), mn1 = fmaxf(m1, mx1);
        const float c0 = __expf(m0 - mn0), c1 = __expf(m1 - mn1);
        float s0 = 0.f, s1 = 0.f;
        #pragma unroll
        for (int nf = 0; nf < 8; nf++) {
            const float e0 = __expf(sac[nf][0] - mn0);
            const float e1 = __expf(sac[nf][1] - mn0);
            const float e2 = __expf(sac[nf][2] - mn1);
            const float e3 = __expf(sac[nf][3] - mn1);
            s0 += e0 + e1; s1 += e2 + e3;
            uint32_t hi0, lo0, hi1, lo1;
            split_pack(e0, e1, hi0, lo0);
            split_pack(e2, e3, hi1, lo1);
            const int coff = nf*8 + 2*tg;
            *(uint32_t*)(sb + W_PH + (w*16 + g    ) * FL + coff) = hi0;
            *(uint32_t*)(sb + W_PL + (w*16 + g    ) * FL + coff) = lo0;
            *(uint32_t*)(sb + W_PH + (w*16 + g + 8) * FL + coff) = hi1;
            *(uint32_t*)(sb + W_PL + (w*16 + g + 8) * FL + coff) = lo1;
        }
        s0 += __shfl_xor_sync(0xffffffffu, s0, 1);
        s0 += __shfl_xor_sync(0xffffffffu, s0, 2);
        s1 += __shfl_xor_sync(0xffffffffu, s1, 1);
        s1 += __shfl_xor_sync(0xffffffffu, s1, 2);
        l0 = l0 * c0 + s0; l1 = l1 * c1 + s1;
        m0 = mn0; m1 = mn1;
        #pragma unroll
        for (int nf = 0; nf < 8; nf++) {
            oac[nf][0] *= c0; oac[nf][1] *= c0;
            oac[nf][2] *= c1; oac[nf][3] *= c1;
        }
        __syncwarp();   // P stores visible to ldmatrix reads within warp

        // ---- O += P @ V : ph@vh + pl@vh + ph@vl ----
        #pragma unroll
        for (int ks = 0; ks < 4; ks++) {
            uint32_t ph[4], pl[4];
            ldm_x4(ph, pA + ks * 32);
            ldm_x4(pl, pA + ks * 32 + PLOFF);
            #pragma unroll
            for (int u = 0; u < 4; u++) {
                uint32_t vh[4], vl[4];
                ldm_x4_t(vh, vA[u] + ks * (16 * FL * 2));
                ldm_x4_t(vl, vA[u] + ks * (16 * FL * 2) + VLOFF);
                mma_bf16_16x8x16(oac[2*u],     ph, vh);
                mma_bf16_16x8x16(oac[2*u],     pl, vh);
                mma_bf16_16x8x16(oac[2*u],     ph, vl);
                mma_bf16_16x8x16(oac[2*u + 1], ph, vh + 2);
                mma_bf16_16x8x16(oac[2*u + 1], pl, vh + 2);
                mma_bf16_16x8x16(oac[2*u + 1], ph, vl + 2);
            }
        }
    }

    // epilogue: merged-head context [B,S,1024]
    const float il0 = 1.0f / l0, il1 = 1.0f / l1;
    const int row0 = qt*FQ + w*16 + g;
    float* ob = g_ctx + ((size_t)b*SEQ + row0) * D_MODEL + h*DEPTH;
    #pragma unroll
    for (int nf = 0; nf < 8; nf++) {
        const int c = nf*8 + 2*tg;
        float2 o0; o0.x = oac[nf][0] * il0; o0.y = oac[nf][1] * il0;
        float2 o1; o1.x = oac[nf][2] * il1; o1.y = oac[nf][3] * il1;
        *(float2*)(ob + c) = o0;
        *(float2*)(ob + (size_t)8 * D_MODEL + c) = o1;
    }
}

// ---------------------------------------------------------------------------
extern "C" void kernel_launch(void* const* d_in, const int* in_sizes, int n_in,
                              void* d_out, int out_size) {
    const float* query = (const float*)d_in[0];
    const float* key   = (const float*)d_in[1];
    const float* value = (const float*)d_in[2];
    const int*   mask  = (const int*)  d_in[3];
    const float* Wq = (const float*)d_in[4];
    const float* bq = (const float*)d_in[5];
    const float* Wk = (const float*)d_in[6];
    const float* bk = (const float*)d_in[7];
    const float* Wv = (const float*)d_in[8];
    const float* bv = (const float*)d_in[9];
    const float* Wo = (const float*)d_in[10];
    const float* bo = (const float*)d_in[11];
    float* out = (float*)d_out;

    cudaFuncSetAttribute(proj_qkv, cudaFuncAttributeMaxDynamicSharedMemorySize, PROJ_SMEM);
    cudaFuncSetAttribute(proj_o,   cudaFuncAttributeMaxDynamicSharedMemorySize, PROJ_SMEM);
    cudaFuncSetAttribute(flash_mma, cudaFuncAttributeMaxDynamicSharedMemorySize, FLASH_SMEM);

    const dim3 gq(D_MODEL / PBN, MTOT / PBM, 3);   // (8, 32, 3)
    proj_qkv<<<gq, 256, PROJ_SMEM>>>(query, key, value, Wq, bq, Wk, bk, Wv, bv);

    flash_mma<<<dim3(SEQ/FQ, NHEADS, BATCH), 256, FLASH_SMEM>>>(mask);

    proj_o<<<dim3(D_MODEL / PBN, MTOT / PBM), 256, PROJ_SMEM>>>(Wo, bo, out);
}

// round 10
// speedup vs baseline: 1.3117x; 1.0002x over previous
#include <cuda_runtime.h>
#include <cuda_bf16.h>
#include <cstdint>
#include <math.h>

#define D_MODEL 1024
#define NHEADS  16
#define DEPTH   64
#define BATCH   2
#define SEQ     2048
#define MTOT    (BATCH*SEQ)   // 4096

// ---------------- scratch (device globals; no allocations allowed) ----------
__device__ float g_q[BATCH*NHEADS*SEQ*DEPTH];   // 16 MB, [B,H,S,64]
__device__ float g_k[BATCH*NHEADS*SEQ*DEPTH];
__device__ float g_v[BATCH*NHEADS*SEQ*DEPTH];
__device__ float g_ctx[BATCH*SEQ*D_MODEL];      // 16 MB, [B,S,1024]

// ---------------- helpers ----------------------------------------------------
__device__ __forceinline__ uint32_t f2tf32(float x) {
    uint32_t r;
    asm("cvt.rna.tf32.f32 %0, %1;" : "=r"(r) : "f"(x));
    return r;
}
__device__ __forceinline__ void mma_tf32_16x8x8(float* d, const uint32_t* a,
                                                const uint32_t* b) {
    asm volatile(
        "mma.sync.aligned.m16n8k8.row.col.f32.tf32.tf32.f32 "
        "{%0,%1,%2,%3}, {%4,%5,%6,%7}, {%8,%9}, {%0,%1,%2,%3};"
        : "+f"(d[0]), "+f"(d[1]), "+f"(d[2]), "+f"(d[3])
        : "r"(a[0]), "r"(a[1]), "r"(a[2]), "r"(a[3]), "r"(b[0]), "r"(b[1]));
}
__device__ __forceinline__ void mma_bf16_16x8x16(float* d, const uint32_t* a,
                                                 const uint32_t* b) {
    asm volatile(
        "mma.sync.aligned.m16n8k16.row.col.f32.bf16.bf16.f32 "
        "{%0,%1,%2,%3}, {%4,%5,%6,%7}, {%8,%9}, {%0,%1,%2,%3};"
        : "+f"(d[0]), "+f"(d[1]), "+f"(d[2]), "+f"(d[3])
        : "r"(a[0]), "r"(a[1]), "r"(a[2]), "r"(a[3]), "r"(b[0]), "r"(b[1]));
}
__device__ __forceinline__ void ldm_x4(uint32_t* r, uint32_t saddr) {
    asm volatile("ldmatrix.sync.aligned.m8n8.x4.shared.b16 {%0,%1,%2,%3}, [%4];"
        : "=r"(r[0]), "=r"(r[1]), "=r"(r[2]), "=r"(r[3]) : "r"(saddr));
}
__device__ __forceinline__ void ldm_x4_t(uint32_t* r, uint32_t saddr) {
    asm volatile("ldmatrix.sync.aligned.m8n8.x4.trans.shared.b16 {%0,%1,%2,%3}, [%4];"
        : "=r"(r[0]), "=r"(r[1]), "=r"(r[2]), "=r"(r[3]) : "r"(saddr));
}
__device__ __forceinline__ uint32_t smem_u32(const void* p) {
    uint32_t a;
    asm("{ .reg .u64 t; cvta.to.shared.u64 t, %1; cvt.u32.u64 %0, t; }"
        : "=r"(a) : "l"(p));
    return a;
}
// pack two floats into bf16x2 (a -> low half, b -> high half), plus residual pack
__device__ __forceinline__ uint32_t bf2pack(float a, float b) {
    uint32_t p;
    asm("cvt.rn.bf16x2.f32 %0, %1, %2;" : "=r"(p) : "f"(b), "f"(a));
    return p;
}
__device__ __forceinline__ void split_pack(float a, float b, uint32_t& hi, uint32_t& lo) {
    hi = bf2pack(a, b);
    const float fa = __uint_as_float(hi << 16);
    const float fb = __uint_as_float(hi & 0xffff0000u);
    lo = bf2pack(a - fa, b - fb);
}
#define CP_ASYNC16(sa, ga) \
    asm volatile("cp.async.ca.shared.global [%0], [%1], 16;" :: "r"(sa), "l"(ga))
#define CP_COMMIT() asm volatile("cp.async.commit_group;" ::: "memory")
#define CP_WAIT(n)  asm volatile("cp.async.wait_group %0;" :: "n"(n) : "memory")

// ============ tf32 tensor-core projection (cp.async pipelined) ==============
constexpr int PBM = 128, PBN = 128, PBK = 32, PLD = PBK + 4;   // PLD=36
constexpr int PROJ_STAGE = PBM * PLD;                           // floats
constexpr int PROJ_SMEM  = 4 * PROJ_STAGE * 4;                  // 73728 bytes

template<int SPLIT>
__device__ __forceinline__
void proj_body(float* smf, const float* __restrict__ A, const float* __restrict__ W,
               const float* __restrict__ bias, float* __restrict__ out) {
    const int tid  = threadIdx.x;
    const int wid  = tid >> 5;
    const int lane = tid & 31;
    const int g    = lane >> 2;
    const int tg   = lane & 3;
    const int wm   = wid >> 2;
    const int wn   = wid & 3;
    const int bm   = blockIdx.y * PBM;
    const int bn   = blockIdx.x * PBN;

    const int lrow8 = lane & 7;
    const int lhalf = (lane >> 3) & 1;
    const int lquad = lane >> 4;

    float* As0 = smf;
    float* Bs0 = smf + 2 * PROJ_STAGE;
    const uint32_t smb = smem_u32(smf);

    uint32_t aAddr[4], bAddr[2];
    #pragma unroll
    for (int mi = 0; mi < 4; mi++)
        aAddr[mi] = smb + ((wm*64 + mi*16 + lhalf*8 + lrow8) * PLD + lquad*4) * 4;
    #pragma unroll
    for (int u = 0; u < 2; u++)
        bAddr[u] = smb + (2*PROJ_STAGE + (wn*32 + (2*u + lquad)*8 + lrow8) * PLD + lhalf*4) * 4;

    float acc[4][4][4] = {};

    auto issue = [&](int s) {
        const int buf = s & 1;
        const int k0  = s * PBK;
        float* As = As0 + buf * PROJ_STAGE;
        float* Bs = Bs0 + buf * PROJ_STAGE;
        #pragma unroll
        for (int i = 0; i < 4; i++) {
            const int idx = tid + i * 256;
            const int r = idx >> 3;
            const int c = (idx & 7) * 4;
            CP_ASYNC16(smem_u32(&As[r * PLD + c]), A + (size_t)(bm + r) * D_MODEL + k0 + c);
            CP_ASYNC16(smem_u32(&Bs[r * PLD + c]), W + (size_t)(bn + r) * D_MODEL + k0 + c);
        }
        CP_COMMIT();
    };

    issue(0);
    for (int s = 0; s < D_MODEL / PBK; s++) {
        const uint32_t bufo = (uint32_t)(s & 1) * PROJ_STAGE * 4;
        if (s + 1 < D_MODEL / PBK) { issue(s + 1); CP_WAIT(1); }
        else                       { CP_WAIT(0); }
        __syncthreads();

        #pragma unroll
        for (int ks = 0; ks < PBK; ks += 8) {
            uint32_t araw[4][4], braw[2][4];
            #pragma unroll
            for (int mi = 0; mi < 4; mi++) ldm_x4(araw[mi], aAddr[mi] + bufo + ks*4);
            #pragma unroll
            for (int u = 0; u < 2; u++)    ldm_x4(braw[u],  bAddr[u]  + bufo + ks*4);

            uint32_t afr[4][4], bfr[4][2];
            #pragma unroll
            for (int mi = 0; mi < 4; mi++)
                #pragma unroll
                for (int e = 0; e < 4; e++)
                    afr[mi][e] = f2tf32(__uint_as_float(araw[mi][e]));
            #pragma unroll
            for (int u = 0; u < 2; u++) {
                bfr[2*u  ][0] = f2tf32(__uint_as_float(braw[u][0]));
                bfr[2*u  ][1] = f2tf32(__uint_as_float(braw[u][1]));
                bfr[2*u+1][0] = f2tf32(__uint_as_float(braw[u][2]));
                bfr[2*u+1][1] = f2tf32(__uint_as_float(braw[u][3]));
            }
            #pragma unroll
            for (int mi = 0; mi < 4; mi++)
                #pragma unroll
                for (int ni = 0; ni < 4; ni++)
                    mma_tf32_16x8x8(acc[mi][ni], afr[mi], bfr[ni]);
        }
        __syncthreads();
    }

    #pragma unroll
    for (int mi = 0; mi < 4; mi++) {
        #pragma unroll
        for (int ni = 0; ni < 4; ni++) {
            const int col = bn + wn * 32 + ni * 8 + tg * 2;
            const float2 bv = *(const float2*)(bias + col);
            #pragma unroll
            for (int half = 0; half < 2; half++) {
                const int m = bm + wm * 64 + mi * 16 + g + half * 8;
                float2 o;
                o.x = acc[mi][ni][half * 2 + 0] + bv.x;
                o.y = acc[mi][ni][half * 2 + 1] + bv.y;
                if (SPLIT) {
                    const int b = m >> 11, sq = m & 2047;
                    const int h = col >> 6, d = col & 63;
                    *(float2*)(out + (((size_t)(b * NHEADS + h) * SEQ) + sq) * DEPTH + d) = o;
                } else {
                    *(float2*)(out + (size_t)m * D_MODEL + col) = o;
                }
            }
        }
    }
}

__global__ __launch_bounds__(256)
void proj_qkv(const float* __restrict__ q, const float* __restrict__ k,
              const float* __restrict__ v,
              const float* __restrict__ Wq, const float* __restrict__ bq,
              const float* __restrict__ Wk, const float* __restrict__ bk,
              const float* __restrict__ Wv, const float* __restrict__ bv) {
    extern __shared__ float smf[];
    const float *A, *W, *bias;
    float* out;
    if (blockIdx.z == 0)      { A = q; W = Wq; bias = bq; out = g_q; }
    else if (blockIdx.z == 1) { A = k; W = Wk; bias = bk; out = g_k; }
    else                      { A = v; W = Wv; bias = bv; out = g_v; }
    proj_body<1>(smf, A, W, bias, out);
}

__global__ __launch_bounds__(256)
void proj_o(const float* __restrict__ W, const float* __restrict__ bias,
            float* __restrict__ out) {
    extern __shared__ float smf[];
    proj_body<0>(smf, g_ctx, W, bias, out);
}

// ================= flash attention v7: split-bf16 3-MMA ======================
// All operands hi+lo bf16 (x = xh + xl). QK^T and P@V computed as
// ah@bh + al@bh + ah@bl (error ~2^-17). m16n8k16 bf16 MMAs, ldmatrix b16
// fragments (trans for V). Row stride 72 bf16 (144B -> conflict-free ldmatrix).
constexpr int FQ  = 128;
constexpr int FK  = 64;
constexpr int FL  = 72;                       // row stride in bf16 units

constexpr int W_QH = 0;                       // 128*72
constexpr int W_QL = W_QH + FQ * FL;          // 9216
constexpr int W_KH = W_QL + FQ * FL;          // 18432
constexpr int W_KL = W_KH + FK * FL;          // 23040
constexpr int W_VH = W_KL + FK * FL;          // 27648
constexpr int W_VL = W_VH + FK * FL;          // 32256
constexpr int W_PH = W_VL + FK * FL;          // 36864
constexpr int W_PL = W_PH + FQ * FL;          // 46080
constexpr int SM_END = W_PL + FQ * FL;        // 55296 bf16 units
constexpr int PEN_B  = SM_END * 2;            // byte offset of pen
constexpr int FLASH_SMEM = PEN_B + FK * 4;    // 110848 bytes

// byte deltas hi->lo buffers
constexpr uint32_t QLOFF = (W_QL - W_QH) * 2;
constexpr uint32_t KLOFF = (W_KL - W_KH) * 2;
constexpr uint32_t VLOFF = (W_VL - W_VH) * 2;
constexpr uint32_t PLOFF = (W_PL - W_PH) * 2;

__global__ __launch_bounds__(256, 2)
void flash_mma(const int* __restrict__ mask) {
    extern __shared__ uint32_t sw[];
    uint16_t* sb = (uint16_t*)sw;
    float* pen = (float*)((char*)sw + PEN_B);

    const int qt = blockIdx.x, h = blockIdx.y, b = blockIdx.z;
    const int tid  = threadIdx.x;
    const int w    = tid >> 5;
    const int lane = tid & 31;
    const int g    = lane >> 2;
    const int tg   = lane & 3;

    const uint32_t swb = smem_u32(sw);
    // A-pattern (Q, P): row = w*16 + (lane&15), col8 = (lane>>4)*8
    const uint32_t arow = w*16 + (lane & 15);
    const uint32_t acol = (lane >> 4) * 8;
    const uint32_t qA = swb + (W_QH + arow * FL + acol) * 2;
    const uint32_t pA = swb + (W_PH + arow * FL + acol) * 2;
    // K B-pattern (non-trans): row = u*16 + (lane>>4)*8 + (lane&7), col8 = ((lane>>3)&1)*8
    uint32_t kA[4];
    #pragma unroll
    for (int u = 0; u < 4; u++)
        kA[u] = swb + (W_KH + (u*16 + (lane >> 4) * 8 + (lane & 7)) * FL
                       + ((lane >> 3) & 1) * 8) * 2;
    // V B-pattern (trans): row = ((lane>>3)&1)*8 + (lane&7) (+ks*16), col = u*16 + (lane>>4)*8
    uint32_t vA[4];
    #pragma unroll
    for (int u = 0; u < 4; u++)
        vA[u] = swb + (W_VH + (((lane >> 3) & 1) * 8 + (lane & 7)) * FL
                       + u*16 + (lane >> 4) * 8) * 2;

    const float* qbase = g_q + ((size_t)(b*NHEADS + h) * SEQ + qt*FQ) * DEPTH;
    const float* kbase = g_k + (size_t)(b*NHEADS + h) * SEQ * DEPTH;
    const float* vbase = g_v + (size_t)(b*NHEADS + h) * SEQ * DEPTH;

    // stage Q (scaled by 1/8), split bf16 hi/lo
    #pragma unroll
    for (int i = 0; i < 8; i++) {
        const int idx = tid + i * 256;
        const int r = idx >> 4, c4 = (idx & 15) << 2;
        float4 v = *(const float4*)(qbase + r * DEPTH + c4);
        v.x *= 0.125f; v.y *= 0.125f; v.z *= 0.125f; v.w *= 0.125f;
        uint2 hi, lo;
        split_pack(v.x, v.y, hi.x, lo.x);
        split_pack(v.z, v.w, hi.y, lo.y);
        *(uint2*)(sb + W_QH + r * FL + c4) = hi;
        *(uint2*)(sb + W_QL + r * FL + c4) = lo;
    }

    // prefetch K/V tile 0 + mask word
    float4 kreg[4], vreg[4];
    #pragma unroll
    for (int j = 0; j < 4; j++) {
        const int slot = tid + j * 256;
        const int r = slot >> 4, c4 = (slot & 15) << 2;
        kreg[j] = *(const float4*)(kbase + (size_t)r * DEPTH + c4);
        vreg[j] = *(const float4*)(vbase + (size_t)r * DEPTH + c4);
    }
    int pmask = (tid < FK) ? mask[b*SEQ + tid] : 0;

    float m0 = -1e30f, m1 = -1e30f, l0 = 0.f, l1 = 0.f;
    float oac[8][4] = {};

    for (int kt = 0; kt < SEQ / FK; kt++) {
        __syncthreads();
        #pragma unroll
        for (int j = 0; j < 4; j++) {
            const int slot = tid + j * 256;
            const int r = slot >> 4, c4 = (slot & 15) << 2;
            uint2 khi, klo, vhi, vlo;
            split_pack(kreg[j].x, kreg[j].y, khi.x, klo.x);
            split_pack(kreg[j].z, kreg[j].w, khi.y, klo.y);
            split_pack(vreg[j].x, vreg[j].y, vhi.x, vlo.x);
            split_pack(vreg[j].z, vreg[j].w, vhi.y, vlo.y);
            *(uint2*)(sb + W_KH + r * FL + c4) = khi;
            *(uint2*)(sb + W_KL + r * FL + c4) = klo;
            *(uint2*)(sb + W_VH + r * FL + c4) = vhi;
            *(uint2*)(sb + W_VL + r * FL + c4) = vlo;
        }
        if (tid < FK)
            pen[tid] = -1e9f * (float)pmask;
        __syncthreads();

        // prefetch next tile (overlaps with MMAs)
        if (kt + 1 < SEQ / FK) {
            const float* kb2 = kbase + (size_t)(kt + 1) * FK * DEPTH;
            const float* vb2 = vbase + (size_t)(kt + 1) * FK * DEPTH;
            #pragma unroll
            for (int j = 0; j < 4; j++) {
                const int slot = tid + j * 256;
                const int r = slot >> 4, c4 = (slot & 15) << 2;
                kreg[j] = *(const float4*)(kb2 + (size_t)r * DEPTH + c4);
                vreg[j] = *(const float4*)(vb2 + (size_t)r * DEPTH + c4);
            }
            if (tid < FK) pmask = mask[b*SEQ + (kt + 1)*FK + tid];
        }

        // ---- S = Q @ K^T : qh@kh + ql@kh + qh@kl ----
        float sac[8][4] = {};
        #pragma unroll
        for (int ks = 0; ks < 4; ks++) {
            uint32_t qh[4], ql[4];
            ldm_x4(qh, qA + ks * 32);
            ldm_x4(ql, qA + ks * 32 + QLOFF);
            #pragma unroll
            for (int u = 0; u < 4; u++) {
                uint32_t kh[4], kl[4];
                ldm_x4(kh, kA[u] + ks * 32);
                ldm_x4(kl, kA[u] + ks * 32 + KLOFF);
                mma_bf16_16x8x16(sac[2*u],     qh, kh);
                mma_bf16_16x8x16(sac[2*u],     ql, kh);
                mma_bf16_16x8x16(sac[2*u],     qh, kl);
                mma_bf16_16x8x16(sac[2*u + 1], qh, kh + 2);
                mma_bf16_16x8x16(sac[2*u + 1], ql, kh + 2);
                mma_bf16_16x8x16(sac[2*u + 1], qh, kl + 2);
            }
        }

        // ---- mask + online softmax ----
        #pragma unroll
        for (int nf = 0; nf < 8; nf++) {
            const float2 pe = *(const float2*)&pen[nf*8 + 2*tg];
            sac[nf][0] += pe.x; sac[nf][1] += pe.y;
            sac[nf][2] += pe.x; sac[nf][3] += pe.y;
        }
        float mx0 = -1e30f, mx1 = -1e30f;
        #pragma unroll
        for (int nf = 0; nf < 8; nf++) {
            mx0 = fmaxf(mx0, fmaxf(sac[nf][0], sac[nf][1]));
            mx1 = fmaxf(mx1, fmaxf(sac[nf][2], sac[nf][3]));
        }
        mx0 = fmaxf(mx0, __shfl_xor_sync(0xffffffffu, mx0, 1));
        mx0 = fmaxf(mx0, __shfl_xor_sync(0xffffffffu, mx0, 2));
        mx1 = fmaxf(mx1, __shfl_xor_sync(0xffffffffu, mx1, 1));
        mx1 = fmaxf(mx1, __shfl_xor_sync(0xffffffffu, mx1, 2));
        const float mn0 = fmaxf(m0, mx0), mn1 = fmaxf(m1, mx1);
        const float c0 = __expf(m0 - mn0), c1 = __expf(m1 - mn1);
        float s0 = 0.f, s1 = 0.f;
        #pragma unroll
        for (int nf = 0; nf < 8; nf++) {
            const float e0 = __expf(sac[nf][0] - mn0);
            const float e1 = __expf(sac[nf][1] - mn0);
            const float e2 = __expf(sac[nf][2] - mn1);
            const float e3 = __expf(sac[nf][3] - mn1);
            s0 += e0 + e1; s1 += e2 + e3;
            uint32_t hi0, lo0, hi1, lo1;
            split_pack(e0, e1, hi0, lo0);
            split_pack(e2, e3, hi1, lo1);
            const int coff = nf*8 + 2*tg;
            *(uint32_t*)(sb + W_PH + (w*16 + g    ) * FL + coff) = hi0;
            *(uint32_t*)(sb + W_PL + (w*16 + g    ) * FL + coff) = lo0;
            *(uint32_t*)(sb + W_PH + (w*16 + g + 8) * FL + coff) = hi1;
            *(uint32_t*)(sb + W_PL + (w*16 + g + 8) * FL + coff) = lo1;
        }
        s0 += __shfl_xor_sync(0xffffffffu, s0, 1);
        s0 += __shfl_xor_sync(0xffffffffu, s0, 2);
        s1 += __shfl_xor_sync(0xffffffffu, s1, 1);
        s1 += __shfl_xor_sync(0xffffffffu, s1, 2);
        l0 = l0 * c0 + s0; l1 = l1 * c1 + s1;
        m0 = mn0; m1 = mn1;
        #pragma unroll
        for (int nf = 0; nf < 8; nf++) {
            oac[nf][0] *= c0; oac[nf][1] *= c0;
            oac[nf][2] *= c1; oac[nf][3] *= c1;
        }
        __syncwarp();   // P stores visible to ldmatrix reads within warp

        // ---- O += P @ V : ph@vh + pl@vh + ph@vl ----
        #pragma unroll
        for (int ks = 0; ks < 4; ks++) {
            uint32_t ph[4], pl[4];
            ldm_x4(ph, pA + ks * 32);
            ldm_x4(pl, pA + ks * 32 + PLOFF);
            #pragma unroll
            for (int u = 0; u < 4; u++) {
                uint32_t vh[4], vl[4];
                ldm_x4_t(vh, vA[u] + ks * (16 * FL * 2));
                ldm_x4_t(vl, vA[u] + ks * (16 * FL * 2) + VLOFF);
                mma_bf16_16x8x16(oac[2*u],     ph, vh);
                mma_bf16_16x8x16(oac[2*u],     pl, vh);
                mma_bf16_16x8x16(oac[2*u],     ph, vl);
                mma_bf16_16x8x16(oac[2*u + 1], ph, vh + 2);
                mma_bf16_16x8x16(oac[2*u + 1], pl, vh + 2);
                mma_bf16_16x8x16(oac[2*u + 1], ph, vl + 2);
            }
        }
    }

    // epilogue: merged-head context [B,S,1024]
    const float il0 = 1.0f / l0, il1 = 1.0f / l1;
    const int row0 = qt*FQ + w*16 + g;
    float* ob = g_ctx + ((size_t)b*SEQ + row0) * D_MODEL + h*DEPTH;
    #pragma unroll
    for (int nf = 0; nf < 8; nf++) {
        const int c = nf*8 + 2*tg;
        float2 o0; o0.x = oac[nf][0] * il0; o0.y = oac[nf][1] * il0;
        float2 o1; o1.x = oac[nf][2] * il1; o1.y = oac[nf][3] * il1;
        *(float2*)(ob + c) = o0;
        *(float2*)(ob + (size_t)8 * D_MODEL + c) = o1;
    }
}

// ---------------------------------------------------------------------------
extern "C" void kernel_launch(void* const* d_in, const int* in_sizes, int n_in,
                              void* d_out, int out_size) {
    const float* query = (const float*)d_in[0];
    const float* key   = (const float*)d_in[1];
    const float* value = (const float*)d_in[2];
    const int*   mask  = (const int*)  d_in[3];
    const float* Wq = (const float*)d_in[4];
    const float* bq = (const float*)d_in[5];
    const float* Wk = (const float*)d_in[6];
    const float* bk = (const float*)d_in[7];
    const float* Wv = (const float*)d_in[8];
    const float* bv = (const float*)d_in[9];
    const float* Wo = (const float*)d_in[10];
    const float* bo = (const float*)d_in[11];
    float* out = (float*)d_out;

    cudaFuncSetAttribute(proj_qkv, cudaFuncAttributeMaxDynamicSharedMemorySize, PROJ_SMEM);
    cudaFuncSetAttribute(proj_o,   cudaFuncAttributeMaxDynamicSharedMemorySize, PROJ_SMEM);
    cudaFuncSetAttribute(flash_mma, cudaFuncAttributeMaxDynamicSharedMemorySize, FLASH_SMEM);

    const dim3 gq(D_MODEL / PBN, MTOT / PBM, 3);   // (8, 32, 3)
    proj_qkv<<<gq, 256, PROJ_SMEM>>>(query, key, value, Wq, bq, Wk, bk, Wv, bv);

    flash_mma<<<dim3(SEQ/FQ, NHEADS, BATCH), 256, FLASH_SMEM>>>(mask);

    proj_o<<<dim3(D_MODEL / PBN, MTOT / PBM), 256, PROJ_SMEM>>>(Wo, bo, out);
}